// round 8
// baseline (speedup 1.0000x reference)
#include <cuda_runtime.h>
#include <cstdint>

#define NCELLS 131072
#define MC     64
#define NBLK   (NCELLS/MC)   // 2048
#define DC     4096

// ---------------- device scratch ----------------
__device__ __align__(16) float d_W1p[32*32*64];      // stage1 B frags
__device__ __align__(16) float d_W2p[32*16*64];      // stage2 B frags
__device__ __align__(16) float d_Wgp[4*49*4*8*64];   // GRU B frags
__device__ float d_xa[128], d_xg[128], d_b2d[128];
__device__ float d_hp[NCELLS*256];
__device__ float d_pfsum[NBLK*256];
__device__ float d_pexpout[NBLK*128];
__device__ float d_pexpsum[NBLK], d_ptsum[NBLK];
__device__ float d_Sf[8*256], d_Df[8*256], d_eor[128], d_es, d_ts;
__device__ float d_fmean[8*256], d_go[256], d_gmean[256];

// ---------------- smem layout (float words) ----------------
#define A1S 260
#define A3S 148
#define SA1 0          // h tile 64x260 (also GRU K-tail A)
#define SA2 16640      // [a1|g1] 64x260, reused for new_h
#define SA3 33280      // [out|tension|1|0s] 64x148
#define ST  42752
#define SE  42816
#define SPAY 42880
#define SMW 42944      // words -> 171776 bytes

__device__ __forceinline__ float rna(float x){
    float r; asm("cvt.rna.tf32.f32 %0, %1;" : "=f"(r) : "f"(x)); return r;
}
__device__ __forceinline__ void mma8(float* c, const uint32_t* a, float2 b){
    asm volatile(
        "mma.sync.aligned.m16n8k8.row.col.f32.tf32.tf32.f32 "
        "{%0,%1,%2,%3}, {%4,%5,%6,%7}, {%8,%9}, {%0,%1,%2,%3};"
        : "+f"(c[0]), "+f"(c[1]), "+f"(c[2]), "+f"(c[3])
        : "r"(a[0]), "r"(a[1]), "r"(a[2]), "r"(a[3]),
          "r"(__float_as_uint(b.x)), "r"(__float_as_uint(b.y)));
}

// ================= kPrep: permute weights into B-fragment layout =================
__global__ void kPrep(const float* __restrict__ x,
                      const float* __restrict__ aw1, const float* __restrict__ ab1,
                      const float* __restrict__ gw1, const float* __restrict__ gb1,
                      const float* __restrict__ aw2, const float* __restrict__ ab2,
                      const float* __restrict__ gw2, const float* __restrict__ gb2,
                      const float* __restrict__ wih, const float* __restrict__ whh,
                      const float* __restrict__ bih, const float* __restrict__ bhh) {
    int tid = blockIdx.x*blockDim.x + threadIdx.x;
    int nth = gridDim.x*blockDim.x;
    for (int i = tid; i < 32*32*64; i += nth){
        int q=i&1, l=(i>>1)&31, nb=(i>>6)&31, ks=i>>11;
        int j=(nb&15)*8+(l>>2), k=ks*8+(l&3)+q*4;
        const float* w = (nb<16)? aw1 : gw1;
        d_W1p[i] = rna(w[j*384 + 128 + k]);
    }
    for (int i = tid; i < 32*16*64; i += nth){
        int q=i&1, l=(i>>1)&31, nb=(i>>6)&15, ks=i>>10;
        int j=nb*8+(l>>2), k=ks*8+(l&3)+q*4;
        float v = (k<128)? aw2[j*128+k] : -gw2[j*128+(k-128)];
        d_W2p[i] = rna(v);
    }
    // GRU: K=[out 0..127 | tension 128 | ones 129 | 0 130..135 | h 136..391]
    for (int i = tid; i < 4*49*4*8*64; i += nth){
        int q=i&1, l=(i>>1)&31, w8=(i>>6)&7, g=(i>>9)&3, rest=i>>11;
        int ks=rest%49, slice=rest/49;
        int d=(slice*8+w8)*8+(l>>2);
        int k=ks*8+(l&3)+q*4;
        float v = 0.f;
        if (g==0){
            if (k<129) v = wih[d*129+k];
            else if (k==129) v = bih[d]+bhh[d];
            else if (k>=136) v = whh[d*256+k-136];
        } else if (g==1){
            int r = 256+d;
            if (k<129) v = wih[r*129+k];
            else if (k==129) v = bih[r]+bhh[r];
            else if (k>=136) v = whh[r*256+k-136];
        } else if (g==2){
            int r = 512+d;
            if (k<129) v = wih[r*129+k];
            else if (k==129) v = bih[r];
        } else {
            int r = 512+d;
            if (k==129) v = bhh[r];
            else if (k>=136) v = whh[r*256+k-136];
        }
        d_Wgp[i] = rna(v);
    }
    if (tid < 128){
        d_b2d[tid] = ab2[tid] - gb2[tid];
        float s = ab1[tid];
        const float* w = aw1 + tid*384;
        for (int k = 0; k < 128; k++) s = fmaf(x[k], w[k], s);
        d_xa[tid] = s;
        s = gb1[tid];
        w = gw1 + tid*384;
        for (int k = 0; k < 128; k++) s = fmaf(x[k], w[k], s);
        d_xg[tid] = s;
    }
}

// ================= kA: tensor-core fused pipeline, 8 fat warps =================
__global__ __launch_bounds__(256,1)
void kA(const float* __restrict__ hiddens, const float* __restrict__ payoffs){
    extern __shared__ float sm[];
    const int t = threadIdx.x, b = blockIdx.x, cell0 = b*MC;
    const int warp = t>>5, lane = t&31, gid = lane>>2, tig = lane&3;

    for (int e = t; e < 64*64; e += 256){
        int row = e>>6, c4 = e&63;
        float4 v = ((const float4*)hiddens)[(size_t)(cell0+row)*64 + c4];
        *(float4*)(sm + SA1 + row*A1S + c4*4) = v;
    }
    if (t < 64){
        sm[SPAY+t] = payoffs[cell0+t];
        float* r3 = sm + SA3 + t*A3S;
        r3[129] = 1.f;
        #pragma unroll
        for (int c = 130; c < 136; c++) r3[c] = 0.f;
    }
    __syncthreads();

    // ---------- stage 1: 32 nb-blocks over 8 warps (4 each) ----------
    {
        float acc[4][4][4];
        #pragma unroll
        for (int nbI = 0; nbI < 4; nbI++){
            int nb = warp + nbI*8;
            const float* xv = ((nb<16)? d_xa : d_xg) + (nb&15)*8 + 2*tig;
            float i0 = xv[0], i1 = xv[1];
            #pragma unroll
            for (int mb = 0; mb < 4; mb++){
                acc[nbI][mb][0]=i0; acc[nbI][mb][1]=i1; acc[nbI][mb][2]=i0; acc[nbI][mb][3]=i1;
            }
        }
        float2 bf[4];
        #pragma unroll
        for (int nbI = 0; nbI < 4; nbI++)
            bf[nbI] = __ldg((const float2*)(d_W1p + (warp + nbI*8)*64 + lane*2));
        #pragma unroll 2
        for (int ks = 0; ks < 32; ks++){
            float2 bn[4];
            if (ks < 31){
                #pragma unroll
                for (int nbI = 0; nbI < 4; nbI++)
                    bn[nbI] = __ldg((const float2*)(d_W1p + ((ks+1)*32 + warp + nbI*8)*64 + lane*2));
            }
            uint32_t af[4][4];
            #pragma unroll
            for (int mb = 0; mb < 4; mb++){
                const float* ap = sm + SA1 + (mb*16+gid)*A1S + ks*8 + tig;
                af[mb][0]=__float_as_uint(ap[0]);   af[mb][1]=__float_as_uint(ap[8*A1S]);
                af[mb][2]=__float_as_uint(ap[4]);   af[mb][3]=__float_as_uint(ap[8*A1S+4]);
            }
            #pragma unroll
            for (int nbI = 0; nbI < 4; nbI++)
                #pragma unroll
                for (int mb = 0; mb < 4; mb++) mma8(acc[nbI][mb], af[mb], bf[nbI]);
            #pragma unroll
            for (int nbI = 0; nbI < 4; nbI++) bf[nbI] = bn[nbI];
        }
        __syncthreads();
        #pragma unroll
        for (int nbI = 0; nbI < 4; nbI++){
            int col = (warp + nbI*8)*8 + 2*tig;
            #pragma unroll
            for (int mb = 0; mb < 4; mb++){
                int row = mb*16 + gid;
                sm[SA2+row*A1S+col]       = fmaxf(acc[nbI][mb][0], 0.f);
                sm[SA2+row*A1S+col+1]     = fmaxf(acc[nbI][mb][1], 0.f);
                sm[SA2+(row+8)*A1S+col]   = fmaxf(acc[nbI][mb][2], 0.f);
                sm[SA2+(row+8)*A1S+col+1] = fmaxf(acc[nbI][mb][3], 0.f);
            }
        }
    }
    __syncthreads();

    // ---------- stage 2: 16 nb-blocks over 8 warps (2 each) ----------
    {
        float ac2[2][4][4];
        #pragma unroll
        for (int nbI = 0; nbI < 2; nbI++){
            int nb = warp + nbI*8;
            float i0 = d_b2d[nb*8+2*tig], i1 = d_b2d[nb*8+2*tig+1];
            #pragma unroll
            for (int mb = 0; mb < 4; mb++){
                ac2[nbI][mb][0]=i0; ac2[nbI][mb][1]=i1; ac2[nbI][mb][2]=i0; ac2[nbI][mb][3]=i1;
            }
        }
        float2 bf[2];
        #pragma unroll
        for (int nbI = 0; nbI < 2; nbI++)
            bf[nbI] = __ldg((const float2*)(d_W2p + (warp + nbI*8)*64 + lane*2));
        #pragma unroll 2
        for (int ks = 0; ks < 32; ks++){
            float2 bn[2];
            if (ks < 31){
                #pragma unroll
                for (int nbI = 0; nbI < 2; nbI++)
                    bn[nbI] = __ldg((const float2*)(d_W2p + ((ks+1)*16 + warp + nbI*8)*64 + lane*2));
            }
            uint32_t af[4][4];
            #pragma unroll
            for (int mb = 0; mb < 4; mb++){
                const float* ap = sm + SA2 + (mb*16+gid)*A1S + ks*8 + tig;
                af[mb][0]=__float_as_uint(ap[0]);   af[mb][1]=__float_as_uint(ap[8*A1S]);
                af[mb][2]=__float_as_uint(ap[4]);   af[mb][3]=__float_as_uint(ap[8*A1S+4]);
            }
            #pragma unroll
            for (int nbI = 0; nbI < 2; nbI++)
                #pragma unroll
                for (int mb = 0; mb < 4; mb++) mma8(ac2[nbI][mb], af[mb], bf[nbI]);
            #pragma unroll
            for (int nbI = 0; nbI < 2; nbI++) bf[nbI] = bn[nbI];
        }
        __syncthreads();
        #pragma unroll
        for (int nbI = 0; nbI < 2; nbI++){
            int col = (warp + nbI*8)*8 + 2*tig;
            #pragma unroll
            for (int mb = 0; mb < 4; mb++){
                int row = mb*16 + gid;
                sm[SA3+row*A3S+col]       = ac2[nbI][mb][0];
                sm[SA3+row*A3S+col+1]     = ac2[nbI][mb][1];
                sm[SA3+(row+8)*A3S+col]   = ac2[nbI][mb][2];
                sm[SA3+(row+8)*A3S+col+1] = ac2[nbI][mb][3];
            }
        }
    }
    __syncthreads();

    // ---------- tension + softmax partials ----------
    if (t < 64){
        const float* o = sm + SA3 + t*A3S;
        float s2 = 0.f;
        for (int j = 0; j < 128; j++){ float v = o[j]; s2 = fmaf(v, v, s2); }
        s2 *= (1.0f/128.0f);
        sm[ST+t] = s2;
        sm[SE+t] = expf(s2);
        sm[SA3+t*A3S+128] = s2;
    }
    __syncthreads();
    if (t < 128){
        float s2 = 0.f;
        for (int c = 0; c < 64; c++) s2 = fmaf(sm[SE+c], sm[SA3+c*A3S+t], s2);
        d_pexpout[b*128+t] = s2;
    } else if (t == 128){
        float s2 = 0.f; for (int c = 0; c < 64; c++) s2 += sm[SE+c];
        d_pexpsum[b] = s2;
    } else if (t == 129){
        float s2 = 0.f; for (int c = 0; c < 64; c++) s2 += sm[ST+c];
        d_ptsum[b] = s2;
    }

    // ---------- GRU: 4 slices; 2 passes; warps 0-3 / 4-7 = slice halves; 2 nb per warp ----------
    const int sg = warp >> 2, w4 = warp & 3;
    for (int sIt = 0; sIt < 2; sIt++){
        const int s = sIt*2 + sg;
        const float* wbS = d_Wgp + (size_t)(s*49*4)*512 + lane*2;
        float aR[2][4][4]={}, aZ[2][4][4]={}, aI[2][4][4]={}, aH[2][4][4]={};

        // ---- phase 1: ks 0..16, gates R,Z,I (A from out-tile SA3) ----
        float2 bR[2], bZ[2], bI[2];
        #pragma unroll
        for (int nbI = 0; nbI < 2; nbI++){
            const float* p = wbS + (w4*2+nbI)*64;
            bR[nbI] = __ldg((const float2*)(p));
            bZ[nbI] = __ldg((const float2*)(p+512));
            bI[nbI] = __ldg((const float2*)(p+1024));
        }
        uint32_t af[4][4];
        #pragma unroll
        for (int mb = 0; mb < 4; mb++){
            const float* ap = sm + SA3 + (mb*16+gid)*A3S + tig;
            af[mb][0]=__float_as_uint(ap[0]);   af[mb][1]=__float_as_uint(ap[8*A3S]);
            af[mb][2]=__float_as_uint(ap[4]);   af[mb][3]=__float_as_uint(ap[8*A3S+4]);
        }
        #pragma unroll 1
        for (int ks = 0; ks < 17; ks++){
            float2 bRn[2], bZn[2], bIn[2];
            uint32_t afn[4][4];
            if (ks < 16){
                #pragma unroll
                for (int nbI = 0; nbI < 2; nbI++){
                    const float* p = wbS + (ks+1)*2048 + (w4*2+nbI)*64;
                    bRn[nbI] = __ldg((const float2*)(p));
                    bZn[nbI] = __ldg((const float2*)(p+512));
                    bIn[nbI] = __ldg((const float2*)(p+1024));
                }
                #pragma unroll
                for (int mb = 0; mb < 4; mb++){
                    const float* ap = sm + SA3 + (mb*16+gid)*A3S + (ks+1)*8 + tig;
                    afn[mb][0]=__float_as_uint(ap[0]);   afn[mb][1]=__float_as_uint(ap[8*A3S]);
                    afn[mb][2]=__float_as_uint(ap[4]);   afn[mb][3]=__float_as_uint(ap[8*A3S+4]);
                }
            }
            #pragma unroll
            for (int nbI = 0; nbI < 2; nbI++)
                #pragma unroll
                for (int mb = 0; mb < 4; mb++){
                    mma8(aR[nbI][mb], af[mb], bR[nbI]);
                    mma8(aZ[nbI][mb], af[mb], bZ[nbI]);
                    mma8(aI[nbI][mb], af[mb], bI[nbI]);
                }
            if (ks == 16){
                #pragma unroll
                for (int nbI = 0; nbI < 2; nbI++){
                    float2 bH16 = __ldg((const float2*)(wbS + 16*2048 + 1536 + (w4*2+nbI)*64));
                    #pragma unroll
                    for (int mb = 0; mb < 4; mb++) mma8(aH[nbI][mb], af[mb], bH16);
                }
            }
            #pragma unroll
            for (int nbI = 0; nbI < 2; nbI++){ bR[nbI]=bRn[nbI]; bZ[nbI]=bZn[nbI]; bI[nbI]=bIn[nbI]; }
            #pragma unroll
            for (int mb = 0; mb < 4; mb++)
                #pragma unroll
                for (int e2 = 0; e2 < 4; e2++) af[mb][e2] = afn[mb][e2];
        }

        // ---- phase 2: ks 17..48, gates R,Z,H (A from h-tile SA1) ----
        float2 bH[2];
        #pragma unroll
        for (int nbI = 0; nbI < 2; nbI++){
            const float* p = wbS + 17*2048 + (w4*2+nbI)*64;
            bR[nbI] = __ldg((const float2*)(p));
            bZ[nbI] = __ldg((const float2*)(p+512));
            bH[nbI] = __ldg((const float2*)(p+1536));
        }
        #pragma unroll
        for (int mb = 0; mb < 4; mb++){
            const float* ap = sm + SA1 + (mb*16+gid)*A1S + (17*8-136) + tig;
            af[mb][0]=__float_as_uint(ap[0]);   af[mb][1]=__float_as_uint(ap[8*A1S]);
            af[mb][2]=__float_as_uint(ap[4]);   af[mb][3]=__float_as_uint(ap[8*A1S+4]);
        }
        #pragma unroll 1
        for (int ks = 17; ks < 49; ks++){
            float2 bRn[2], bZn[2], bHn[2];
            uint32_t afn[4][4];
            if (ks < 48){
                #pragma unroll
                for (int nbI = 0; nbI < 2; nbI++){
                    const float* p = wbS + (ks+1)*2048 + (w4*2+nbI)*64;
                    bRn[nbI] = __ldg((const float2*)(p));
                    bZn[nbI] = __ldg((const float2*)(p+512));
                    bHn[nbI] = __ldg((const float2*)(p+1536));
                }
                #pragma unroll
                for (int mb = 0; mb < 4; mb++){
                    const float* ap = sm + SA1 + (mb*16+gid)*A1S + ((ks+1)*8-136) + tig;
                    afn[mb][0]=__float_as_uint(ap[0]);   afn[mb][1]=__float_as_uint(ap[8*A1S]);
                    afn[mb][2]=__float_as_uint(ap[4]);   afn[mb][3]=__float_as_uint(ap[8*A1S+4]);
                }
            }
            #pragma unroll
            for (int nbI = 0; nbI < 2; nbI++)
                #pragma unroll
                for (int mb = 0; mb < 4; mb++){
                    mma8(aR[nbI][mb], af[mb], bR[nbI]);
                    mma8(aZ[nbI][mb], af[mb], bZ[nbI]);
                    mma8(aH[nbI][mb], af[mb], bH[nbI]);
                }
            #pragma unroll
            for (int nbI = 0; nbI < 2; nbI++){ bR[nbI]=bRn[nbI]; bZ[nbI]=bZn[nbI]; bH[nbI]=bHn[nbI]; }
            #pragma unroll
            for (int mb = 0; mb < 4; mb++)
                #pragma unroll
                for (int e2 = 0; e2 < 4; e2++) af[mb][e2] = afn[mb][e2];
        }

        // ---- epilogue: gates + payoff + clamp ----
        #pragma unroll
        for (int nbI = 0; nbI < 2; nbI++){
            int d0 = s*64 + (w4*2+nbI)*8 + 2*tig;
            #pragma unroll
            for (int mb = 0; mb < 4; mb++){
                #pragma unroll
                for (int hf = 0; hf < 2; hf++){
                    int row = mb*16 + gid + hf*8;
                    int cell = cell0 + row;
                    float2 hh = *(const float2*)(hiddens + (size_t)cell*256 + d0);
                    float sc = fmaf(0.02f, sm[SPAY+row], 0.9f);
                    #pragma unroll
                    for (int q = 0; q < 2; q++){
                        int e = hf*2 + q;
                        float r  = 1.0f/(1.0f + expf(-aR[nbI][mb][e]));
                        float z  = 1.0f/(1.0f + expf(-aZ[nbI][mb][e]));
                        float nn = tanhf(fmaf(r, aH[nbI][mb][e], aI[nbI][mb][e]));
                        float h  = q ? hh.y : hh.x;
                        float v  = (1.0f - z)*nn + z*h;
                        v *= sc;
                        v = fminf(10.0f, fmaxf(-10.0f, v));
                        d_hp[(size_t)cell*256 + d0 + q] = v;
                        sm[SA2 + row*A1S + d0 + q] = v;
                    }
                }
            }
        }
    }
    __syncthreads();
    // per-block faction partial sums
    {
        float ssum = 0.f;
        for (int c = 0; c < 64; c++) ssum += sm[SA2 + c*A1S + t];
        d_pfsum[b*256 + t] = ssum;
    }
}

// ================= kB1: deterministic reductions =================
__global__ void kB1() {
    int tid = blockIdx.x*blockDim.x + threadIdx.x;
    if (tid < 2048){
        int f = tid>>8, d = tid&255;
        float S = 0.f, D = 0.f;
        const float* p = d_pfsum + (size_t)(f*256)*256 + d;
        for (int b2 = 0; b2 < 256; b2++){
            float v = p[(size_t)b2*256];
            S += v;
            if (b2 < 64) D += v;
        }
        d_Sf[tid] = S; d_Df[tid] = D;
    } else if (tid < 2176){
        int j = tid - 2048; float s = 0.f;
        for (int b2 = 0; b2 < NBLK; b2++) s += d_pexpout[b2*128+j];
        d_eor[j] = s;
    } else if (tid == 2176){
        float s = 0.f; for (int b2 = 0; b2 < NBLK; b2++) s += d_pexpsum[b2];
        d_es = s;
    } else if (tid == 2177){
        float s = 0.f; for (int b2 = 0; b2 < NBLK; b2++) s += d_ptsum[b2];
        d_ts = s;
    }
}

// ================= kB2: stats + pred + avg_tension =================
__global__ void kB2(const float* __restrict__ head_w, const float* __restrict__ head_b,
                    const int* __restrict__ stepp, float* __restrict__ out) {
    int t = threadIdx.x;
    int step = *stepp;
    if (t < 256){
        float Sfv[8];
        #pragma unroll
        for (int f = 0; f < 8; f++) Sfv[f] = d_Sf[f*256+t];
        float go = 0.f;
        #pragma unroll
        for (int f = 0; f < 8; f++) go += Sfv[f]*(1.0f/16384.0f);
        go *= 0.125f;
        d_go[t] = go;
        float gsum = 0.f;
        #pragma unroll
        for (int f = 0; f < 8; f++){
            float fm = Sfv[f]*(1.0f/16384.0f);
            d_fmean[f*256+t] = fm;
            float Tf = Sfv[f];
            if (step > 5){
                float D = d_Df[f*256+t];
                Tf += 0.15f*(4096.0f*go - 0.85f*D - 4096.0f*0.15f*fm);
            }
            gsum += Tf;
        }
        d_gmean[t] = gsum*(1.0f/131072.0f);
    }
    if (t < 128){
        float inv = 1.0f/d_es;
        float s = head_b[t];
        const float* hw = head_w + t*128;
        for (int j = 0; j < 128; j++) s = fmaf(d_eor[j]*inv, hw[j], s);
        out[t] = s;
    }
    if (t == 0) out[128] = d_ts*(1.0f/131072.0f);
}

// ================= threefry (partitionable) + XLA erf_inv =================
__device__ __forceinline__ uint32_t threefry_bits(uint32_t x0, uint32_t x1) {
    const uint32_t ks0 = 0u, ks1 = 42u, ks2 = 0x1BD11BF0u;
    x0 += ks0; x1 += ks1;
#define RND(R) { x0 += x1; x1 = (x1 << R) | (x1 >> (32 - R)); x1 ^= x0; }
    RND(13) RND(15) RND(26) RND(6)   x0 += ks1; x1 += ks2 + 1u;
    RND(17) RND(29) RND(16) RND(24)  x0 += ks2; x1 += ks0 + 2u;
    RND(13) RND(15) RND(26) RND(6)   x0 += ks0; x1 += ks1 + 3u;
    RND(17) RND(29) RND(16) RND(24)  x0 += ks1; x1 += ks2 + 4u;
    RND(13) RND(15) RND(26) RND(6)   x0 += ks2; x1 += ks0 + 5u;
#undef RND
    return x0 ^ x1;
}
__device__ __forceinline__ float erfinv_xla(float x) {
    float w = -log1pf(-x*x);
    float p;
    if (w < 5.0f){
        w -= 2.5f;
        p = 2.81022636e-08f;
        p = fmaf(p, w, 3.43273939e-07f);  p = fmaf(p, w, -3.5233877e-06f);
        p = fmaf(p, w, -4.39150654e-06f); p = fmaf(p, w, 0.00021858087f);
        p = fmaf(p, w, -0.00125372503f);  p = fmaf(p, w, -0.00417768164f);
        p = fmaf(p, w, 0.246640727f);     p = fmaf(p, w, 1.50140941f);
    } else {
        w = sqrtf(w) - 3.0f;
        p = -0.000200214257f;
        p = fmaf(p, w, 0.000100950558f);  p = fmaf(p, w, 0.00134934322f);
        p = fmaf(p, w, -0.00367342844f);  p = fmaf(p, w, 0.00573950773f);
        p = fmaf(p, w, -0.0076224613f);   p = fmaf(p, w, 0.00943887047f);
        p = fmaf(p, w, 1.00167406f);      p = fmaf(p, w, 2.83297682f);
    }
    return p*x;
}
__device__ __forceinline__ float bits_to_normal(uint32_t bits) {
    float u01 = __uint_as_float((bits >> 9) | 0x3f800000u) - 1.0f;
    float u = u01*2.0f + (-0.99999994f);
    u = fmaxf(-0.99999994f, u);
    return 1.4142135623730951f*erfinv_xla(u);
}

// ================= kC: sync/debate/pull/noise/clamp =================
__global__ void kC(const int* __restrict__ lact, const int* __restrict__ stepp,
                   float* __restrict__ out) {
    const int cell = blockIdx.x;
    const int d = threadIdx.x;
    const int step = *stepp;
    const int l0 = lact[cell];
    const int l1 = lact[cell + 65536];
    uint32_t m = (uint32_t)cell*256u + (uint32_t)d;
    float n0 = l0 ? 0.f : bits_to_normal(threefry_bits(0u, m));
    float n1 = l1 ? 0.f : bits_to_normal(threefry_bits(0u, m + 16777216u));
    const float gm = d_gmean[d];
    const float go = d_go[d];
    #pragma unroll
    for (int half = 0; half < 2; half++){
        int c = cell + half*65536;
        float n = half ? n1 : n0;
        float coop = (float)(half ? l1 : l0);
        float v = d_hp[(size_t)c*256 + d];
        int f = c >> 14;
        v = 0.85f*v + 0.15f*d_fmean[f*256+d];
        if (step > 5 && (c & 16383) < DC) v = 0.85f*v + 0.15f*go;
        v += 0.05f*coop*(gm - v);
        v += 0.02f*(1.0f - coop)*n;
        v = fminf(10.0f, fmaxf(-10.0f, v));
        out[129 + (size_t)c*256 + d] = v;
    }
}

// ================= launch =================
extern "C" void kernel_launch(void* const* d_in, const int* in_sizes, int n_in,
                              void* d_out, int out_size) {
    const float* x       = (const float*)d_in[0];
    const float* payoffs = (const float*)d_in[1];
    const int*   last    = (const int*)d_in[2];
    const int*   step    = (const int*)d_in[3];
    const float* hiddens = (const float*)d_in[4];
    const float* a_w1    = (const float*)d_in[5];
    const float* a_b1    = (const float*)d_in[6];
    const float* a_w2    = (const float*)d_in[7];
    const float* a_b2    = (const float*)d_in[8];
    const float* g_w1    = (const float*)d_in[9];
    const float* g_b1    = (const float*)d_in[10];
    const float* g_w2    = (const float*)d_in[11];
    const float* g_b2    = (const float*)d_in[12];
    const float* gru_wih = (const float*)d_in[13];
    const float* gru_whh = (const float*)d_in[14];
    const float* gru_bih = (const float*)d_in[15];
    const float* gru_bhh = (const float*)d_in[16];
    const float* head_w  = (const float*)d_in[17];
    const float* head_b  = (const float*)d_in[18];
    float* out = (float*)d_out;

    cudaFuncSetAttribute(kA, cudaFuncAttributeMaxDynamicSharedMemorySize, SMW*4);

    kPrep<<<512, 256>>>(x, a_w1, a_b1, g_w1, g_b1, a_w2, a_b2, g_w2, g_b2,
                        gru_wih, gru_whh, gru_bih, gru_bhh);
    kA<<<NBLK, 256, SMW*4>>>(hiddens, payoffs);
    kB1<<<18, 128>>>();
    kB2<<<1, 256>>>(head_w, head_b, step, out);
    kC<<<65536, 256>>>(last, step, out);
}

// round 9
// speedup vs baseline: 1.8935x; 1.8935x over previous
#include <cuda_runtime.h>
#include <cuda_fp16.h>
#include <cstdint>

#define NCELLS 131072
#define MC     64
#define NBLK   (NCELLS/MC)   // 2048
#define DC     4096

// ---------------- device scratch ----------------
__device__ __align__(16) uint2 d_W1h[16*32*32];        // stage1 B frags (fp16)
__device__ __align__(16) uint2 d_W2h[16*16*32];        // stage2 B frags
__device__ __align__(16) uint2 d_Wgh[4*25*4*8*32];     // GRU B frags
__device__ float d_xa[128], d_xg[128], d_b2d[128];
__device__ float d_hp[NCELLS*256];
__device__ float d_pfsum[NBLK*256];
__device__ float d_pexpout[NBLK*128];
__device__ float d_pexpsum[NBLK], d_ptsum[NBLK];
__device__ float d_Sf[8*256], d_Df[8*256], d_eor[128], d_es, d_ts;
__device__ float d_fmean[8*256], d_go[256], d_gmean[256];

// ---------------- smem layout (u32 words) ----------------
#define HSW 132
#define OUW 76
#define S_HS 0            // h tile 64x(128 half2 + pad)
#define S_A2 8448         // [a1|g1] tile 64x(128 half2 + pad)
#define S_OU 16896        // [out|tension|1|0] 64x(72 half2 + pad)
#define S_T  21760
#define S_E  21824
#define S_PAY 21888
#define SMW  21952        // words -> 87808 bytes

__device__ __forceinline__ uint32_t f2h2(float a, float b){
    __half2 h = __floats2half2_rn(a, b);
    return *reinterpret_cast<uint32_t*>(&h);
}
__device__ __forceinline__ float2 h2f2(uint32_t w){
    __half2 h = *reinterpret_cast<__half2*>(&w);
    return __half22float2(h);
}
__device__ __forceinline__ void mma16(float* c, const uint32_t* a, uint2 b){
    asm volatile(
        "mma.sync.aligned.m16n8k16.row.col.f32.f16.f16.f32 "
        "{%0,%1,%2,%3}, {%4,%5,%6,%7}, {%8,%9}, {%0,%1,%2,%3};"
        : "+f"(c[0]), "+f"(c[1]), "+f"(c[2]), "+f"(c[3])
        : "r"(a[0]), "r"(a[1]), "r"(a[2]), "r"(a[3]),
          "r"(b.x), "r"(b.y));
}

// GRU weight value: K-map [out 0..127 | tension 128 | ones 129 | 0 | h 144..399]
__device__ __forceinline__ float gvv(int gate, int d, int k,
        const float* wih, const float* whh, const float* bih, const float* bhh){
    if (gate <= 1){
        int r = d + (gate==1 ? 256 : 0);
        if (k < 129) return wih[r*129+k];
        if (k == 129) return bih[r]+bhh[r];
        if (k >= 144) return whh[r*256+k-144];
        return 0.f;
    } else if (gate == 2){
        int r = 512 + d;
        if (k < 129) return wih[r*129+k];
        if (k == 129) return bih[r];
        return 0.f;
    } else {
        int r = 512 + d;
        if (k == 129) return bhh[r];
        if (k >= 144) return whh[r*256+k-144];
        return 0.f;
    }
}

// ================= kPrep =================
__global__ void kPrep(const float* __restrict__ x,
                      const float* __restrict__ aw1, const float* __restrict__ ab1,
                      const float* __restrict__ gw1, const float* __restrict__ gb1,
                      const float* __restrict__ aw2, const float* __restrict__ ab2,
                      const float* __restrict__ gw2, const float* __restrict__ gb2,
                      const float* __restrict__ wih, const float* __restrict__ whh,
                      const float* __restrict__ bih, const float* __restrict__ bhh) {
    int tid = blockIdx.x*blockDim.x + threadIdx.x;
    int nth = gridDim.x*blockDim.x;
    for (int i = tid; i < 16*32*32; i += nth){
        int lane=i&31, nb=(i>>5)&31, ks=i>>10;
        int t4=lane&3, g=lane>>2;
        int n = nb*8+g;
        const float* w = (n<128)? aw1 : gw1;
        int j = n & 127;
        int k0 = ks*16 + t4*2;
        const float* r = w + j*384 + 128;
        uint2 v; v.x = f2h2(r[k0], r[k0+1]); v.y = f2h2(r[k0+8], r[k0+9]);
        d_W1h[i] = v;
    }
    for (int i = tid; i < 16*16*32; i += nth){
        int lane=i&31, nb=(i>>5)&15, ks=i>>9;
        int t4=lane&3, g=lane>>2;
        int n = nb*8+g;
        int k0 = ks*16 + t4*2;
        float vv[4];
        #pragma unroll
        for (int q = 0; q < 4; q++){
            int k = k0 + (q>>1)*8 + (q&1);
            vv[q] = (k<128)? aw2[n*128+k] : -gw2[n*128+k-128];
        }
        uint2 v; v.x = f2h2(vv[0], vv[1]); v.y = f2h2(vv[2], vv[3]);
        d_W2h[i] = v;
    }
    for (int i = tid; i < 4*25*4*8*32; i += nth){
        int lane=i&31, nb=(i>>5)&7, gate=(i>>8)&3, rest=i>>10;
        int ks = rest%25, s = rest/25;
        int t4=lane&3, g=lane>>2;
        int d = s*64 + nb*8 + g;
        int k0 = ks*16 + t4*2;
        uint2 v;
        v.x = f2h2(gvv(gate,d,k0,wih,whh,bih,bhh),   gvv(gate,d,k0+1,wih,whh,bih,bhh));
        v.y = f2h2(gvv(gate,d,k0+8,wih,whh,bih,bhh), gvv(gate,d,k0+9,wih,whh,bih,bhh));
        d_Wgh[i] = v;
    }
    if (tid < 128){
        d_b2d[tid] = ab2[tid] - gb2[tid];
        float s = ab1[tid];
        const float* w = aw1 + tid*384;
        for (int k = 0; k < 128; k++) s = fmaf(x[k], w[k], s);
        d_xa[tid] = s;
        s = gb1[tid];
        w = gw1 + tid*384;
        for (int k = 0; k < 128; k++) s = fmaf(x[k], w[k], s);
        d_xg[tid] = s;
    }
}

// ================= kA: fp16 tensor-core fused pipeline =================
__global__ __launch_bounds__(256,2)
void kA(const float* __restrict__ hiddens, const float* __restrict__ payoffs){
    extern __shared__ uint32_t smu[];
    float* smf = (float*)smu;
    const int t = threadIdx.x, b = blockIdx.x, cell0 = b*MC;
    const int warp = t>>5, lane = t&31, gid = lane>>2, tig = lane&3;

    // load h tile -> fp16 half2
    for (int e = t; e < 64*64; e += 256){
        int row = e>>6, c4 = e&63;
        float4 v = ((const float4*)hiddens)[(size_t)(cell0+row)*64 + c4];
        smu[S_HS + row*HSW + c4*2]     = f2h2(v.x, v.y);
        smu[S_HS + row*HSW + c4*2 + 1] = f2h2(v.z, v.w);
    }
    if (t < 64) smf[S_PAY+t] = payoffs[cell0+t];
    __syncthreads();

    // ---------- stage 1: 32 nb over 8 warps, 2 passes of 2 nb ----------
    #pragma unroll 1
    for (int pass = 0; pass < 2; pass++){
        float acc[2][4][4];
        #pragma unroll
        for (int nbI = 0; nbI < 2; nbI++){
            int nb = warp + (pass*2+nbI)*8;
            int n = nb*8 + 2*tig;
            const float* xv = (nb < 16) ? (d_xa + n) : (d_xg + n - 128);
            float i0 = xv[0], i1 = xv[1];
            #pragma unroll
            for (int mb = 0; mb < 4; mb++){
                acc[nbI][mb][0]=i0; acc[nbI][mb][1]=i1; acc[nbI][mb][2]=i0; acc[nbI][mb][3]=i1;
            }
        }
        uint2 bf[2];
        #pragma unroll
        for (int nbI = 0; nbI < 2; nbI++)
            bf[nbI] = __ldg(d_W1h + (warp + (pass*2+nbI)*8)*32 + lane);
        #pragma unroll
        for (int ks = 0; ks < 16; ks++){
            uint2 bn[2];
            if (ks < 15){
                #pragma unroll
                for (int nbI = 0; nbI < 2; nbI++)
                    bn[nbI] = __ldg(d_W1h + ((ks+1)*32 + warp + (pass*2+nbI)*8)*32 + lane);
            }
            uint32_t af[4][4];
            #pragma unroll
            for (int mb = 0; mb < 4; mb++){
                const uint32_t* ap = smu + S_HS + (mb*16+gid)*HSW + ks*8 + tig;
                af[mb][0]=ap[0]; af[mb][1]=ap[8*HSW]; af[mb][2]=ap[4]; af[mb][3]=ap[8*HSW+4];
            }
            #pragma unroll
            for (int nbI = 0; nbI < 2; nbI++)
                #pragma unroll
                for (int mb = 0; mb < 4; mb++) mma16(acc[nbI][mb], af[mb], bf[nbI]);
            bf[0]=bn[0]; bf[1]=bn[1];
        }
        #pragma unroll
        for (int nbI = 0; nbI < 2; nbI++){
            int wcol = (warp + (pass*2+nbI)*8)*4 + tig;
            #pragma unroll
            for (int mb = 0; mb < 4; mb++){
                int row = mb*16 + gid;
                smu[S_A2 + row*HSW + wcol] =
                    f2h2(fmaxf(acc[nbI][mb][0],0.f), fmaxf(acc[nbI][mb][1],0.f));
                smu[S_A2 + (row+8)*HSW + wcol] =
                    f2h2(fmaxf(acc[nbI][mb][2],0.f), fmaxf(acc[nbI][mb][3],0.f));
            }
        }
    }
    __syncthreads();

    // ---------- stage 2: 16 nb over 8 warps (2 each), K=256 ----------
    {
        float ac2[2][4][4];
        #pragma unroll
        for (int nbI = 0; nbI < 2; nbI++){
            int n = (warp + nbI*8)*8 + 2*tig;
            float i0 = d_b2d[n], i1 = d_b2d[n+1];
            #pragma unroll
            for (int mb = 0; mb < 4; mb++){
                ac2[nbI][mb][0]=i0; ac2[nbI][mb][1]=i1; ac2[nbI][mb][2]=i0; ac2[nbI][mb][3]=i1;
            }
        }
        uint2 bf[2];
        #pragma unroll
        for (int nbI = 0; nbI < 2; nbI++)
            bf[nbI] = __ldg(d_W2h + (warp + nbI*8)*32 + lane);
        #pragma unroll
        for (int ks = 0; ks < 16; ks++){
            uint2 bn[2];
            if (ks < 15){
                #pragma unroll
                for (int nbI = 0; nbI < 2; nbI++)
                    bn[nbI] = __ldg(d_W2h + ((ks+1)*16 + warp + nbI*8)*32 + lane);
            }
            uint32_t af[4][4];
            #pragma unroll
            for (int mb = 0; mb < 4; mb++){
                const uint32_t* ap = smu + S_A2 + (mb*16+gid)*HSW + ks*8 + tig;
                af[mb][0]=ap[0]; af[mb][1]=ap[8*HSW]; af[mb][2]=ap[4]; af[mb][3]=ap[8*HSW+4];
            }
            #pragma unroll
            for (int nbI = 0; nbI < 2; nbI++)
                #pragma unroll
                for (int mb = 0; mb < 4; mb++) mma16(ac2[nbI][mb], af[mb], bf[nbI]);
            bf[0]=bn[0]; bf[1]=bn[1];
        }
        #pragma unroll
        for (int nbI = 0; nbI < 2; nbI++){
            int wcol = (warp + nbI*8)*4 + tig;
            #pragma unroll
            for (int mb = 0; mb < 4; mb++){
                int row = mb*16 + gid;
                smu[S_OU + row*OUW + wcol]     = f2h2(ac2[nbI][mb][0], ac2[nbI][mb][1]);
                smu[S_OU + (row+8)*OUW + wcol] = f2h2(ac2[nbI][mb][2], ac2[nbI][mb][3]);
            }
        }
    }
    __syncthreads();

    // ---------- tension + fill K-tail cols ----------
    if (t < 64){
        float s2 = 0.f;
        const uint32_t* o = smu + S_OU + t*OUW;
        #pragma unroll 8
        for (int j = 0; j < 64; j++){
            float2 v = h2f2(o[j]);
            s2 = fmaf(v.x, v.x, s2); s2 = fmaf(v.y, v.y, s2);
        }
        s2 *= (1.0f/128.0f);
        smf[S_T+t] = s2;
        smf[S_E+t] = expf(s2);
        uint32_t* ow = smu + S_OU + t*OUW;
        ow[64] = f2h2(s2, 1.0f);
        #pragma unroll
        for (int c = 65; c < 72; c++) ow[c] = 0u;
    }
    __syncthreads();
    if (t < 128){
        float s2 = 0.f;
        int wj = t >> 1, hi = t & 1;
        for (int c = 0; c < 64; c++){
            float2 v = h2f2(smu[S_OU + c*OUW + wj]);
            s2 = fmaf(smf[S_E+c], hi ? v.y : v.x, s2);
        }
        d_pexpout[b*128+t] = s2;
    } else if (t == 128){
        float s2 = 0.f; for (int c = 0; c < 64; c++) s2 += smf[S_E+c];
        d_pexpsum[b] = s2;
    } else if (t == 129){
        float s2 = 0.f; for (int c = 0; c < 64; c++) s2 += smf[S_T+c];
        d_ptsum[b] = s2;
    }

    // ---------- GRU: 4 slices, 1 nb per warp, fused 4 gates ----------
    #pragma unroll 1
    for (int s = 0; s < 4; s++){
        float aR[4][4]={}, aZ[4][4]={}, aI[4][4]={}, aH[4][4]={};
        const uint2* wg0 = d_Wgh + ((s*25*4 + 0)*8 + warp)*32 + lane;
        // gate g at kstep ks: offset ((ks*4 + g)*8)*32 relative to wg0
        uint2 bR = __ldg(wg0);
        uint2 bZ = __ldg(wg0 + 256);   // g=1: 1*8*32
        uint2 bI = __ldg(wg0 + 512);   // g=2
        uint32_t af[4][4];
        #pragma unroll
        for (int mb = 0; mb < 4; mb++){
            const uint32_t* ap = smu + S_OU + (mb*16+gid)*OUW + tig;
            af[mb][0]=ap[0]; af[mb][1]=ap[8*OUW]; af[mb][2]=ap[4]; af[mb][3]=ap[8*OUW+4];
        }
        #pragma unroll
        for (int ks = 0; ks <= 8; ks++){
            uint2 bRn, bZn, bIn; uint32_t afn[4][4];
            if (ks < 8){
                const uint2* wn = wg0 + (ks+1)*1024;
                bRn = __ldg(wn); bZn = __ldg(wn + 256); bIn = __ldg(wn + 512);
                #pragma unroll
                for (int mb = 0; mb < 4; mb++){
                    const uint32_t* ap = smu + S_OU + (mb*16+gid)*OUW + (ks+1)*8 + tig;
                    afn[mb][0]=ap[0]; afn[mb][1]=ap[8*OUW]; afn[mb][2]=ap[4]; afn[mb][3]=ap[8*OUW+4];
                }
            }
            #pragma unroll
            for (int mb = 0; mb < 4; mb++){
                mma16(aR[mb], af[mb], bR);
                mma16(aZ[mb], af[mb], bZ);
                mma16(aI[mb], af[mb], bI);
            }
            if (ks == 8){
                uint2 bH8 = __ldg(wg0 + 8*1024 + 768);  // g=3
                #pragma unroll
                for (int mb = 0; mb < 4; mb++) mma16(aH[mb], af[mb], bH8);
            }
            bR=bRn; bZ=bZn; bI=bIn;
            #pragma unroll
            for (int mb = 0; mb < 4; mb++)
                #pragma unroll
                for (int e2 = 0; e2 < 4; e2++) af[mb][e2] = afn[mb][e2];
        }
        // phase 2: ks 9..24 (A = h tile, h2 offset ks*8-72)
        {
            const uint2* w9 = wg0 + 9*1024;
            bR = __ldg(w9); bZ = __ldg(w9 + 256);
        }
        uint2 bH = __ldg(wg0 + 9*1024 + 768);
        #pragma unroll
        for (int mb = 0; mb < 4; mb++){
            const uint32_t* ap = smu + S_HS + (mb*16+gid)*HSW + tig;   // ks=9 -> offset 0
            af[mb][0]=ap[0]; af[mb][1]=ap[8*HSW]; af[mb][2]=ap[4]; af[mb][3]=ap[8*HSW+4];
        }
        #pragma unroll
        for (int ks = 9; ks <= 24; ks++){
            uint2 bRn, bZn, bHn; uint32_t afn[4][4];
            if (ks < 24){
                const uint2* wn = wg0 + (ks+1)*1024;
                bRn = __ldg(wn); bZn = __ldg(wn + 256); bHn = __ldg(wn + 768);
                #pragma unroll
                for (int mb = 0; mb < 4; mb++){
                    const uint32_t* ap = smu + S_HS + (mb*16+gid)*HSW + ((ks+1)*8-72) + tig;
                    afn[mb][0]=ap[0]; afn[mb][1]=ap[8*HSW]; afn[mb][2]=ap[4]; afn[mb][3]=ap[8*HSW+4];
                }
            }
            #pragma unroll
            for (int mb = 0; mb < 4; mb++){
                mma16(aR[mb], af[mb], bR);
                mma16(aZ[mb], af[mb], bZ);
                mma16(aH[mb], af[mb], bH);
            }
            bR=bRn; bZ=bZn; bH=bHn;
            #pragma unroll
            for (int mb = 0; mb < 4; mb++)
                #pragma unroll
                for (int e2 = 0; e2 < 4; e2++) af[mb][e2] = afn[mb][e2];
        }

        // epilogue: gates + payoff + clamp; pfsum via shfl butterfly
        int d0 = s*64 + warp*8 + 2*tig;
        float cs0 = 0.f, cs1 = 0.f;
        #pragma unroll
        for (int mb = 0; mb < 4; mb++){
            #pragma unroll
            for (int hf = 0; hf < 2; hf++){
                int row = mb*16 + gid + hf*8;
                int cell = cell0 + row;
                float2 hh = *(const float2*)(hiddens + (size_t)cell*256 + d0);
                float sc = fmaf(0.02f, smf[S_PAY+row], 0.9f);
                float v0, v1;
                {
                    int e = hf*2;
                    float r  = 1.0f/(1.0f + expf(-aR[mb][e]));
                    float z  = 1.0f/(1.0f + expf(-aZ[mb][e]));
                    float nn = tanhf(fmaf(r, aH[mb][e], aI[mb][e]));
                    v0 = ((1.0f - z)*nn + z*hh.x) * sc;
                    v0 = fminf(10.0f, fmaxf(-10.0f, v0));
                    r  = 1.0f/(1.0f + expf(-aR[mb][e+1]));
                    z  = 1.0f/(1.0f + expf(-aZ[mb][e+1]));
                    nn = tanhf(fmaf(r, aH[mb][e+1], aI[mb][e+1]));
                    v1 = ((1.0f - z)*nn + z*hh.y) * sc;
                    v1 = fminf(10.0f, fmaxf(-10.0f, v1));
                }
                *(float2*)(d_hp + (size_t)cell*256 + d0) = make_float2(v0, v1);
                cs0 += v0; cs1 += v1;
            }
        }
        cs0 += __shfl_xor_sync(0xffffffffu, cs0, 4);
        cs0 += __shfl_xor_sync(0xffffffffu, cs0, 8);
        cs0 += __shfl_xor_sync(0xffffffffu, cs0, 16);
        cs1 += __shfl_xor_sync(0xffffffffu, cs1, 4);
        cs1 += __shfl_xor_sync(0xffffffffu, cs1, 8);
        cs1 += __shfl_xor_sync(0xffffffffu, cs1, 16);
        if (gid == 0){
            d_pfsum[b*256 + d0]     = cs0;
            d_pfsum[b*256 + d0 + 1] = cs1;
        }
    }
}

// ================= kB1: deterministic reductions =================
__global__ void kB1() {
    int tid = blockIdx.x*blockDim.x + threadIdx.x;
    if (tid < 2048){
        int f = tid>>8, d = tid&255;
        float S = 0.f, D = 0.f;
        const float* p = d_pfsum + (size_t)(f*256)*256 + d;
        for (int b2 = 0; b2 < 256; b2++){
            float v = p[(size_t)b2*256];
            S += v;
            if (b2 < 64) D += v;
        }
        d_Sf[tid] = S; d_Df[tid] = D;
    } else if (tid < 2176){
        int j = tid - 2048; float s = 0.f;
        for (int b2 = 0; b2 < NBLK; b2++) s += d_pexpout[b2*128+j];
        d_eor[j] = s;
    } else if (tid == 2176){
        float s = 0.f; for (int b2 = 0; b2 < NBLK; b2++) s += d_pexpsum[b2];
        d_es = s;
    } else if (tid == 2177){
        float s = 0.f; for (int b2 = 0; b2 < NBLK; b2++) s += d_ptsum[b2];
        d_ts = s;
    }
}

// ================= kB2: stats + pred + avg_tension =================
__global__ void kB2(const float* __restrict__ head_w, const float* __restrict__ head_b,
                    const int* __restrict__ stepp, float* __restrict__ out) {
    int t = threadIdx.x;
    int step = *stepp;
    if (t < 256){
        float Sfv[8];
        #pragma unroll
        for (int f = 0; f < 8; f++) Sfv[f] = d_Sf[f*256+t];
        float go = 0.f;
        #pragma unroll
        for (int f = 0; f < 8; f++) go += Sfv[f]*(1.0f/16384.0f);
        go *= 0.125f;
        d_go[t] = go;
        float gsum = 0.f;
        #pragma unroll
        for (int f = 0; f < 8; f++){
            float fm = Sfv[f]*(1.0f/16384.0f);
            d_fmean[f*256+t] = fm;
            float Tf = Sfv[f];
            if (step > 5){
                float D = d_Df[f*256+t];
                Tf += 0.15f*(4096.0f*go - 0.85f*D - 4096.0f*0.15f*fm);
            }
            gsum += Tf;
        }
        d_gmean[t] = gsum*(1.0f/131072.0f);
    }
    if (t < 128){
        float inv = 1.0f/d_es;
        float s = head_b[t];
        const float* hw = head_w + t*128;
        for (int j = 0; j < 128; j++) s = fmaf(d_eor[j]*inv, hw[j], s);
        out[t] = s;
    }
    if (t == 0) out[128] = d_ts*(1.0f/131072.0f);
}

// ================= threefry (partitionable) + XLA erf_inv =================
__device__ __forceinline__ uint32_t threefry_bits(uint32_t x0, uint32_t x1) {
    const uint32_t ks0 = 0u, ks1 = 42u, ks2 = 0x1BD11BF0u;
    x0 += ks0; x1 += ks1;
#define RND(R) { x0 += x1; x1 = (x1 << R) | (x1 >> (32 - R)); x1 ^= x0; }
    RND(13) RND(15) RND(26) RND(6)   x0 += ks1; x1 += ks2 + 1u;
    RND(17) RND(29) RND(16) RND(24)  x0 += ks2; x1 += ks0 + 2u;
    RND(13) RND(15) RND(26) RND(6)   x0 += ks0; x1 += ks1 + 3u;
    RND(17) RND(29) RND(16) RND(24)  x0 += ks1; x1 += ks2 + 4u;
    RND(13) RND(15) RND(26) RND(6)   x0 += ks2; x1 += ks0 + 5u;
#undef RND
    return x0 ^ x1;
}
__device__ __forceinline__ float erfinv_xla(float x) {
    float w = -log1pf(-x*x);
    float p;
    if (w < 5.0f){
        w -= 2.5f;
        p = 2.81022636e-08f;
        p = fmaf(p, w, 3.43273939e-07f);  p = fmaf(p, w, -3.5233877e-06f);
        p = fmaf(p, w, -4.39150654e-06f); p = fmaf(p, w, 0.00021858087f);
        p = fmaf(p, w, -0.00125372503f);  p = fmaf(p, w, -0.00417768164f);
        p = fmaf(p, w, 0.246640727f);     p = fmaf(p, w, 1.50140941f);
    } else {
        w = sqrtf(w) - 3.0f;
        p = -0.000200214257f;
        p = fmaf(p, w, 0.000100950558f);  p = fmaf(p, w, 0.00134934322f);
        p = fmaf(p, w, -0.00367342844f);  p = fmaf(p, w, 0.00573950773f);
        p = fmaf(p, w, -0.0076224613f);   p = fmaf(p, w, 0.00943887047f);
        p = fmaf(p, w, 1.00167406f);      p = fmaf(p, w, 2.83297682f);
    }
    return p*x;
}
__device__ __forceinline__ float bits_to_normal(uint32_t bits) {
    float u01 = __uint_as_float((bits >> 9) | 0x3f800000u) - 1.0f;
    float u = u01*2.0f + (-0.99999994f);
    u = fmaxf(-0.99999994f, u);
    return 1.4142135623730951f*erfinv_xla(u);
}

// ================= kC: sync/debate/pull/noise/clamp =================
__global__ void kC(const int* __restrict__ lact, const int* __restrict__ stepp,
                   float* __restrict__ out) {
    const int cell = blockIdx.x;
    const int d = threadIdx.x;
    const int step = *stepp;
    const int l0 = lact[cell];
    const int l1 = lact[cell + 65536];
    uint32_t m = (uint32_t)cell*256u + (uint32_t)d;
    float n0 = l0 ? 0.f : bits_to_normal(threefry_bits(0u, m));
    float n1 = l1 ? 0.f : bits_to_normal(threefry_bits(0u, m + 16777216u));
    const float gm = d_gmean[d];
    const float go = d_go[d];
    #pragma unroll
    for (int half = 0; half < 2; half++){
        int c = cell + half*65536;
        float n = half ? n1 : n0;
        float coop = (float)(half ? l1 : l0);
        float v = d_hp[(size_t)c*256 + d];
        int f = c >> 14;
        v = 0.85f*v + 0.15f*d_fmean[f*256+d];
        if (step > 5 && (c & 16383) < DC) v = 0.85f*v + 0.15f*go;
        v += 0.05f*coop*(gm - v);
        v += 0.02f*(1.0f - coop)*n;
        v = fminf(10.0f, fmaxf(-10.0f, v));
        out[129 + (size_t)c*256 + d] = v;
    }
}

// ================= launch =================
extern "C" void kernel_launch(void* const* d_in, const int* in_sizes, int n_in,
                              void* d_out, int out_size) {
    const float* x       = (const float*)d_in[0];
    const float* payoffs = (const float*)d_in[1];
    const int*   last    = (const int*)d_in[2];
    const int*   step    = (const int*)d_in[3];
    const float* hiddens = (const float*)d_in[4];
    const float* a_w1    = (const float*)d_in[5];
    const float* a_b1    = (const float*)d_in[6];
    const float* a_w2    = (const float*)d_in[7];
    const float* a_b2    = (const float*)d_in[8];
    const float* g_w1    = (const float*)d_in[9];
    const float* g_b1    = (const float*)d_in[10];
    const float* g_w2    = (const float*)d_in[11];
    const float* g_b2    = (const float*)d_in[12];
    const float* gru_wih = (const float*)d_in[13];
    const float* gru_whh = (const float*)d_in[14];
    const float* gru_bih = (const float*)d_in[15];
    const float* gru_bhh = (const float*)d_in[16];
    const float* head_w  = (const float*)d_in[17];
    const float* head_b  = (const float*)d_in[18];
    float* out = (float*)d_out;

    cudaFuncSetAttribute(kA, cudaFuncAttributeMaxDynamicSharedMemorySize, SMW*4);

    kPrep<<<512, 256>>>(x, a_w1, a_b1, g_w1, g_b1, a_w2, a_b2, g_w2, g_b2,
                        gru_wih, gru_whh, gru_bih, gru_bhh);
    kA<<<NBLK, 256, SMW*4>>>(hiddens, payoffs);
    kB1<<<18, 128>>>();
    kB2<<<1, 256>>>(head_w, head_b, step, out);
    kC<<<65536, 256>>>(last, step, out);
}

// round 10
// speedup vs baseline: 1.9792x; 1.0453x over previous
#include <cuda_runtime.h>
#include <cuda_fp16.h>
#include <cstdint>

#define NCELLS 131072
#define MC     64
#define NBLK   (NCELLS/MC)   // 2048
#define DC     4096

// ---------------- device scratch ----------------
__device__ __align__(16) uint2 d_W1h[16*32*32];        // stage1 B frags (fp16)
__device__ __align__(16) uint2 d_W2h[16*16*32];        // stage2 B frags
__device__ __align__(16) uint2 d_Wgh[4*25*4*8*32];     // GRU B frags
__device__ float d_xa[128], d_xg[128], d_b2d[128];
__device__ float d_hp[NCELLS*256];
__device__ float d_noise[NCELLS*256];                  // 0.02*(1-coop)*n, precomputed
__device__ float d_pfsum[NBLK*256];
__device__ float d_pexpout[NBLK*128];
__device__ float d_pexpsum[NBLK], d_ptsum[NBLK];
__device__ float d_SfP[2048*8], d_eorP[128*16], d_esP[16], d_tsP[16];
__device__ float d_Sf[8*256], d_Df[8*256], d_eor[128], d_es, d_ts;
__device__ float d_fmean[8*256], d_go[256], d_gmean[256];

// ---------------- smem layout (u32 words) ----------------
#define HSW 132
#define OUW 76
#define S_HS 0
#define S_A2 8448
#define S_OU 16896
#define S_T  21760
#define S_E  21824
#define S_PAY 21888
#define SMW  21952        // words -> 87808 bytes

__device__ __forceinline__ uint32_t f2h2(float a, float b){
    __half2 h = __floats2half2_rn(a, b);
    return *reinterpret_cast<uint32_t*>(&h);
}
__device__ __forceinline__ float2 h2f2(uint32_t w){
    __half2 h = *reinterpret_cast<__half2*>(&w);
    return __half22float2(h);
}
__device__ __forceinline__ void mma16(float* c, const uint32_t* a, uint2 b){
    asm volatile(
        "mma.sync.aligned.m16n8k16.row.col.f32.f16.f16.f32 "
        "{%0,%1,%2,%3}, {%4,%5,%6,%7}, {%8,%9}, {%0,%1,%2,%3};"
        : "+f"(c[0]), "+f"(c[1]), "+f"(c[2]), "+f"(c[3])
        : "r"(a[0]), "r"(a[1]), "r"(a[2]), "r"(a[3]),
          "r"(b.x), "r"(b.y));
}

// GRU weight value: K-map [out 0..127 | tension 128 | ones 129 | 0 | h 144..399]
__device__ __forceinline__ float gvv(int gate, int d, int k,
        const float* wih, const float* whh, const float* bih, const float* bhh){
    if (gate <= 1){
        int r = d + (gate==1 ? 256 : 0);
        if (k < 129) return wih[r*129+k];
        if (k == 129) return bih[r]+bhh[r];
        if (k >= 144) return whh[r*256+k-144];
        return 0.f;
    } else if (gate == 2){
        int r = 512 + d;
        if (k < 129) return wih[r*129+k];
        if (k == 129) return bih[r];
        return 0.f;
    } else {
        int r = 512 + d;
        if (k == 129) return bhh[r];
        if (k >= 144) return whh[r*256+k-144];
        return 0.f;
    }
}

// ================= kPrep =================
__global__ void kPrep(const float* __restrict__ x,
                      const float* __restrict__ aw1, const float* __restrict__ ab1,
                      const float* __restrict__ gw1, const float* __restrict__ gb1,
                      const float* __restrict__ aw2, const float* __restrict__ ab2,
                      const float* __restrict__ gw2, const float* __restrict__ gb2,
                      const float* __restrict__ wih, const float* __restrict__ whh,
                      const float* __restrict__ bih, const float* __restrict__ bhh) {
    int tid = blockIdx.x*blockDim.x + threadIdx.x;
    int nth = gridDim.x*blockDim.x;
    for (int i = tid; i < 16*32*32; i += nth){
        int lane=i&31, nb=(i>>5)&31, ks=i>>10;
        int t4=lane&3, g=lane>>2;
        int n = nb*8+g;
        const float* w = (n<128)? aw1 : gw1;
        int j = n & 127;
        int k0 = ks*16 + t4*2;
        const float* r = w + j*384 + 128;
        uint2 v; v.x = f2h2(r[k0], r[k0+1]); v.y = f2h2(r[k0+8], r[k0+9]);
        d_W1h[i] = v;
    }
    for (int i = tid; i < 16*16*32; i += nth){
        int lane=i&31, nb=(i>>5)&15, ks=i>>9;
        int t4=lane&3, g=lane>>2;
        int n = nb*8+g;
        int k0 = ks*16 + t4*2;
        float vv[4];
        #pragma unroll
        for (int q = 0; q < 4; q++){
            int k = k0 + (q>>1)*8 + (q&1);
            vv[q] = (k<128)? aw2[n*128+k] : -gw2[n*128+k-128];
        }
        uint2 v; v.x = f2h2(vv[0], vv[1]); v.y = f2h2(vv[2], vv[3]);
        d_W2h[i] = v;
    }
    for (int i = tid; i < 4*25*4*8*32; i += nth){
        int lane=i&31, nb=(i>>5)&7, gate=(i>>8)&3, rest=i>>10;
        int ks = rest%25, s = rest/25;
        int t4=lane&3, g=lane>>2;
        int d = s*64 + nb*8 + g;
        int k0 = ks*16 + t4*2;
        uint2 v;
        v.x = f2h2(gvv(gate,d,k0,wih,whh,bih,bhh),   gvv(gate,d,k0+1,wih,whh,bih,bhh));
        v.y = f2h2(gvv(gate,d,k0+8,wih,whh,bih,bhh), gvv(gate,d,k0+9,wih,whh,bih,bhh));
        d_Wgh[i] = v;
    }
    if (tid < 128){
        d_b2d[tid] = ab2[tid] - gb2[tid];
        float s = ab1[tid];
        const float* w = aw1 + tid*384;
        for (int k = 0; k < 128; k++) s = fmaf(x[k], w[k], s);
        d_xa[tid] = s;
        s = gb1[tid];
        w = gw1 + tid*384;
        for (int k = 0; k < 128; k++) s = fmaf(x[k], w[k], s);
        d_xg[tid] = s;
    }
}

// ================= kA: fp16 tensor-core fused pipeline =================
__global__ __launch_bounds__(256,2)
void kA(const float* __restrict__ hiddens, const float* __restrict__ payoffs){
    extern __shared__ uint32_t smu[];
    float* smf = (float*)smu;
    const int t = threadIdx.x, b = blockIdx.x, cell0 = b*MC;
    const int warp = t>>5, lane = t&31, gid = lane>>2, tig = lane&3;

    for (int e = t; e < 64*64; e += 256){
        int row = e>>6, c4 = e&63;
        float4 v = ((const float4*)hiddens)[(size_t)(cell0+row)*64 + c4];
        smu[S_HS + row*HSW + c4*2]     = f2h2(v.x, v.y);
        smu[S_HS + row*HSW + c4*2 + 1] = f2h2(v.z, v.w);
    }
    if (t < 64) smf[S_PAY+t] = payoffs[cell0+t];
    __syncthreads();

    // ---------- stage 1 ----------
    #pragma unroll 1
    for (int pass = 0; pass < 2; pass++){
        float acc[2][4][4];
        #pragma unroll
        for (int nbI = 0; nbI < 2; nbI++){
            int nb = warp + (pass*2+nbI)*8;
            int n = nb*8 + 2*tig;
            const float* xv = (nb < 16) ? (d_xa + n) : (d_xg + n - 128);
            float i0 = xv[0], i1 = xv[1];
            #pragma unroll
            for (int mb = 0; mb < 4; mb++){
                acc[nbI][mb][0]=i0; acc[nbI][mb][1]=i1; acc[nbI][mb][2]=i0; acc[nbI][mb][3]=i1;
            }
        }
        uint2 bf[2];
        #pragma unroll
        for (int nbI = 0; nbI < 2; nbI++)
            bf[nbI] = __ldg(d_W1h + (warp + (pass*2+nbI)*8)*32 + lane);
        #pragma unroll
        for (int ks = 0; ks < 16; ks++){
            uint2 bn[2];
            if (ks < 15){
                #pragma unroll
                for (int nbI = 0; nbI < 2; nbI++)
                    bn[nbI] = __ldg(d_W1h + ((ks+1)*32 + warp + (pass*2+nbI)*8)*32 + lane);
            }
            uint32_t af[4][4];
            #pragma unroll
            for (int mb = 0; mb < 4; mb++){
                const uint32_t* ap = smu + S_HS + (mb*16+gid)*HSW + ks*8 + tig;
                af[mb][0]=ap[0]; af[mb][1]=ap[8*HSW]; af[mb][2]=ap[4]; af[mb][3]=ap[8*HSW+4];
            }
            #pragma unroll
            for (int nbI = 0; nbI < 2; nbI++)
                #pragma unroll
                for (int mb = 0; mb < 4; mb++) mma16(acc[nbI][mb], af[mb], bf[nbI]);
            bf[0]=bn[0]; bf[1]=bn[1];
        }
        #pragma unroll
        for (int nbI = 0; nbI < 2; nbI++){
            int wcol = (warp + (pass*2+nbI)*8)*4 + tig;
            #pragma unroll
            for (int mb = 0; mb < 4; mb++){
                int row = mb*16 + gid;
                smu[S_A2 + row*HSW + wcol] =
                    f2h2(fmaxf(acc[nbI][mb][0],0.f), fmaxf(acc[nbI][mb][1],0.f));
                smu[S_A2 + (row+8)*HSW + wcol] =
                    f2h2(fmaxf(acc[nbI][mb][2],0.f), fmaxf(acc[nbI][mb][3],0.f));
            }
        }
    }
    __syncthreads();

    // ---------- stage 2 ----------
    {
        float ac2[2][4][4];
        #pragma unroll
        for (int nbI = 0; nbI < 2; nbI++){
            int n = (warp + nbI*8)*8 + 2*tig;
            float i0 = d_b2d[n], i1 = d_b2d[n+1];
            #pragma unroll
            for (int mb = 0; mb < 4; mb++){
                ac2[nbI][mb][0]=i0; ac2[nbI][mb][1]=i1; ac2[nbI][mb][2]=i0; ac2[nbI][mb][3]=i1;
            }
        }
        uint2 bf[2];
        #pragma unroll
        for (int nbI = 0; nbI < 2; nbI++)
            bf[nbI] = __ldg(d_W2h + (warp + nbI*8)*32 + lane);
        #pragma unroll
        for (int ks = 0; ks < 16; ks++){
            uint2 bn[2];
            if (ks < 15){
                #pragma unroll
                for (int nbI = 0; nbI < 2; nbI++)
                    bn[nbI] = __ldg(d_W2h + ((ks+1)*16 + warp + nbI*8)*32 + lane);
            }
            uint32_t af[4][4];
            #pragma unroll
            for (int mb = 0; mb < 4; mb++){
                const uint32_t* ap = smu + S_A2 + (mb*16+gid)*HSW + ks*8 + tig;
                af[mb][0]=ap[0]; af[mb][1]=ap[8*HSW]; af[mb][2]=ap[4]; af[mb][3]=ap[8*HSW+4];
            }
            #pragma unroll
            for (int nbI = 0; nbI < 2; nbI++)
                #pragma unroll
                for (int mb = 0; mb < 4; mb++) mma16(ac2[nbI][mb], af[mb], bf[nbI]);
            bf[0]=bn[0]; bf[1]=bn[1];
        }
        #pragma unroll
        for (int nbI = 0; nbI < 2; nbI++){
            int wcol = (warp + nbI*8)*4 + tig;
            #pragma unroll
            for (int mb = 0; mb < 4; mb++){
                int row = mb*16 + gid;
                smu[S_OU + row*OUW + wcol]     = f2h2(ac2[nbI][mb][0], ac2[nbI][mb][1]);
                smu[S_OU + (row+8)*OUW + wcol] = f2h2(ac2[nbI][mb][2], ac2[nbI][mb][3]);
            }
        }
    }
    __syncthreads();

    // ---------- tension + fill K-tail cols ----------
    if (t < 64){
        float s2 = 0.f;
        const uint32_t* o = smu + S_OU + t*OUW;
        #pragma unroll 8
        for (int j = 0; j < 64; j++){
            float2 v = h2f2(o[j]);
            s2 = fmaf(v.x, v.x, s2); s2 = fmaf(v.y, v.y, s2);
        }
        s2 *= (1.0f/128.0f);
        smf[S_T+t] = s2;
        smf[S_E+t] = expf(s2);
        uint32_t* ow = smu + S_OU + t*OUW;
        ow[64] = f2h2(s2, 1.0f);
        #pragma unroll
        for (int c = 65; c < 72; c++) ow[c] = 0u;
    }
    __syncthreads();
    if (t < 128){
        float s2 = 0.f;
        int wj = t >> 1, hi = t & 1;
        for (int c = 0; c < 64; c++){
            float2 v = h2f2(smu[S_OU + c*OUW + wj]);
            s2 = fmaf(smf[S_E+c], hi ? v.y : v.x, s2);
        }
        d_pexpout[b*128+t] = s2;
    } else if (t == 128){
        float s2 = 0.f; for (int c = 0; c < 64; c++) s2 += smf[S_E+c];
        d_pexpsum[b] = s2;
    } else if (t == 129){
        float s2 = 0.f; for (int c = 0; c < 64; c++) s2 += smf[S_T+c];
        d_ptsum[b] = s2;
    }

    // ---------- GRU: 4 slices, 1 nb per warp, fused 4 gates ----------
    #pragma unroll 1
    for (int s = 0; s < 4; s++){
        float aR[4][4]={}, aZ[4][4]={}, aI[4][4]={}, aH[4][4]={};
        const uint2* wg0 = d_Wgh + ((s*25*4 + 0)*8 + warp)*32 + lane;
        uint2 bR = __ldg(wg0);
        uint2 bZ = __ldg(wg0 + 256);
        uint2 bI = __ldg(wg0 + 512);
        uint32_t af[4][4];
        #pragma unroll
        for (int mb = 0; mb < 4; mb++){
            const uint32_t* ap = smu + S_OU + (mb*16+gid)*OUW + tig;
            af[mb][0]=ap[0]; af[mb][1]=ap[8*OUW]; af[mb][2]=ap[4]; af[mb][3]=ap[8*OUW+4];
        }
        #pragma unroll
        for (int ks = 0; ks <= 8; ks++){
            uint2 bRn, bZn, bIn; uint32_t afn[4][4];
            if (ks < 8){
                const uint2* wn = wg0 + (ks+1)*1024;
                bRn = __ldg(wn); bZn = __ldg(wn + 256); bIn = __ldg(wn + 512);
                #pragma unroll
                for (int mb = 0; mb < 4; mb++){
                    const uint32_t* ap = smu + S_OU + (mb*16+gid)*OUW + (ks+1)*8 + tig;
                    afn[mb][0]=ap[0]; afn[mb][1]=ap[8*OUW]; afn[mb][2]=ap[4]; afn[mb][3]=ap[8*OUW+4];
                }
            }
            #pragma unroll
            for (int mb = 0; mb < 4; mb++){
                mma16(aR[mb], af[mb], bR);
                mma16(aZ[mb], af[mb], bZ);
                mma16(aI[mb], af[mb], bI);
            }
            if (ks == 8){
                uint2 bH8 = __ldg(wg0 + 8*1024 + 768);
                #pragma unroll
                for (int mb = 0; mb < 4; mb++) mma16(aH[mb], af[mb], bH8);
            }
            bR=bRn; bZ=bZn; bI=bIn;
            #pragma unroll
            for (int mb = 0; mb < 4; mb++)
                #pragma unroll
                for (int e2 = 0; e2 < 4; e2++) af[mb][e2] = afn[mb][e2];
        }
        {
            const uint2* w9 = wg0 + 9*1024;
            bR = __ldg(w9); bZ = __ldg(w9 + 256);
        }
        uint2 bH = __ldg(wg0 + 9*1024 + 768);
        #pragma unroll
        for (int mb = 0; mb < 4; mb++){
            const uint32_t* ap = smu + S_HS + (mb*16+gid)*HSW + tig;
            af[mb][0]=ap[0]; af[mb][1]=ap[8*HSW]; af[mb][2]=ap[4]; af[mb][3]=ap[8*HSW+4];
        }
        #pragma unroll
        for (int ks = 9; ks <= 24; ks++){
            uint2 bRn, bZn, bHn; uint32_t afn[4][4];
            if (ks < 24){
                const uint2* wn = wg0 + (ks+1)*1024;
                bRn = __ldg(wn); bZn = __ldg(wn + 256); bHn = __ldg(wn + 768);
                #pragma unroll
                for (int mb = 0; mb < 4; mb++){
                    const uint32_t* ap = smu + S_HS + (mb*16+gid)*HSW + ((ks+1)*8-72) + tig;
                    afn[mb][0]=ap[0]; afn[mb][1]=ap[8*HSW]; afn[mb][2]=ap[4]; afn[mb][3]=ap[8*HSW+4];
                }
            }
            #pragma unroll
            for (int mb = 0; mb < 4; mb++){
                mma16(aR[mb], af[mb], bR);
                mma16(aZ[mb], af[mb], bZ);
                mma16(aH[mb], af[mb], bH);
            }
            bR=bRn; bZ=bZn; bH=bHn;
            #pragma unroll
            for (int mb = 0; mb < 4; mb++)
                #pragma unroll
                for (int e2 = 0; e2 < 4; e2++) af[mb][e2] = afn[mb][e2];
        }

        int d0 = s*64 + warp*8 + 2*tig;
        float cs0 = 0.f, cs1 = 0.f;
        #pragma unroll
        for (int mb = 0; mb < 4; mb++){
            #pragma unroll
            for (int hf = 0; hf < 2; hf++){
                int row = mb*16 + gid + hf*8;
                int cell = cell0 + row;
                float2 hh = *(const float2*)(hiddens + (size_t)cell*256 + d0);
                float sc = fmaf(0.02f, smf[S_PAY+row], 0.9f);
                float v0, v1;
                {
                    int e = hf*2;
                    float r  = 1.0f/(1.0f + expf(-aR[mb][e]));
                    float z  = 1.0f/(1.0f + expf(-aZ[mb][e]));
                    float nn = tanhf(fmaf(r, aH[mb][e], aI[mb][e]));
                    v0 = ((1.0f - z)*nn + z*hh.x) * sc;
                    v0 = fminf(10.0f, fmaxf(-10.0f, v0));
                    r  = 1.0f/(1.0f + expf(-aR[mb][e+1]));
                    z  = 1.0f/(1.0f + expf(-aZ[mb][e+1]));
                    nn = tanhf(fmaf(r, aH[mb][e+1], aI[mb][e+1]));
                    v1 = ((1.0f - z)*nn + z*hh.y) * sc;
                    v1 = fminf(10.0f, fmaxf(-10.0f, v1));
                }
                *(float2*)(d_hp + (size_t)cell*256 + d0) = make_float2(v0, v1);
                cs0 += v0; cs1 += v1;
            }
        }
        cs0 += __shfl_xor_sync(0xffffffffu, cs0, 4);
        cs0 += __shfl_xor_sync(0xffffffffu, cs0, 8);
        cs0 += __shfl_xor_sync(0xffffffffu, cs0, 16);
        cs1 += __shfl_xor_sync(0xffffffffu, cs1, 4);
        cs1 += __shfl_xor_sync(0xffffffffu, cs1, 8);
        cs1 += __shfl_xor_sync(0xffffffffu, cs1, 16);
        if (gid == 0){
            d_pfsum[b*256 + d0]     = cs0;
            d_pfsum[b*256 + d0 + 1] = cs1;
        }
    }
}

// ================= threefry (partitionable) + XLA erf_inv =================
__device__ __forceinline__ uint32_t threefry_bits(uint32_t x0, uint32_t x1) {
    const uint32_t ks0 = 0u, ks1 = 42u, ks2 = 0x1BD11BF0u;
    x0 += ks0; x1 += ks1;
#define RND(R) { x0 += x1; x1 = (x1 << R) | (x1 >> (32 - R)); x1 ^= x0; }
    RND(13) RND(15) RND(26) RND(6)   x0 += ks1; x1 += ks2 + 1u;
    RND(17) RND(29) RND(16) RND(24)  x0 += ks2; x1 += ks0 + 2u;
    RND(13) RND(15) RND(26) RND(6)   x0 += ks0; x1 += ks1 + 3u;
    RND(17) RND(29) RND(16) RND(24)  x0 += ks1; x1 += ks2 + 4u;
    RND(13) RND(15) RND(26) RND(6)   x0 += ks2; x1 += ks0 + 5u;
#undef RND
    return x0 ^ x1;
}
__device__ __forceinline__ float erfinv_xla(float x) {
    float w = -log1pf(-x*x);
    float p;
    if (w < 5.0f){
        w -= 2.5f;
        p = 2.81022636e-08f;
        p = fmaf(p, w, 3.43273939e-07f);  p = fmaf(p, w, -3.5233877e-06f);
        p = fmaf(p, w, -4.39150654e-06f); p = fmaf(p, w, 0.00021858087f);
        p = fmaf(p, w, -0.00125372503f);  p = fmaf(p, w, -0.00417768164f);
        p = fmaf(p, w, 0.246640727f);     p = fmaf(p, w, 1.50140941f);
    } else {
        w = sqrtf(w) - 3.0f;
        p = -0.000200214257f;
        p = fmaf(p, w, 0.000100950558f);  p = fmaf(p, w, 0.00134934322f);
        p = fmaf(p, w, -0.00367342844f);  p = fmaf(p, w, 0.00573950773f);
        p = fmaf(p, w, -0.0076224613f);   p = fmaf(p, w, 0.00943887047f);
        p = fmaf(p, w, 1.00167406f);      p = fmaf(p, w, 2.83297682f);
    }
    return p*x;
}
__device__ __forceinline__ float bits_to_normal(uint32_t bits) {
    float u01 = __uint_as_float((bits >> 9) | 0x3f800000u) - 1.0f;
    float u = u01*2.0f + (-0.99999994f);
    u = fmaxf(-0.99999994f, u);
    return 1.4142135623730951f*erfinv_xla(u);
}

// ================= kNoise: depends only on last_action; runs on fork stream =================
__global__ void kNoise(const int* __restrict__ lact){
    const int cell = blockIdx.x;
    const int d = threadIdx.x;
    const int l0 = lact[cell];
    const int l1 = lact[cell + 65536];
    uint32_t m = (uint32_t)cell*256u + (uint32_t)d;
    float n0 = l0 ? 0.f : 0.02f*bits_to_normal(threefry_bits(0u, m));
    float n1 = l1 ? 0.f : 0.02f*bits_to_normal(threefry_bits(0u, m + 16777216u));
    d_noise[(size_t)cell*256 + d] = n0;
    d_noise[(size_t)(cell+65536)*256 + d] = n1;
}

// ================= kB1a/kB1b: parallel deterministic reductions =================
__global__ void kB1a() {
    int tid = blockIdx.x*blockDim.x + threadIdx.x;
    if (tid < 16384){
        int c = tid & 7, fd = tid >> 3;
        int f = fd >> 8, d = fd & 255;
        const float* p = d_pfsum + (size_t)(f*256 + c*32)*256 + d;
        float S = 0.f;
        #pragma unroll 8
        for (int i = 0; i < 32; i++) S += p[(size_t)i*256];
        d_SfP[tid] = S;
    } else if (tid < 18432){
        int t2 = tid - 16384;
        int c = t2 & 15, j = t2 >> 4;
        const float* p = d_pexpout + (size_t)(c*128)*128 + j;
        float s = 0.f;
        #pragma unroll 8
        for (int i = 0; i < 128; i++) s += p[(size_t)i*128];
        d_eorP[j*16+c] = s;
    } else if (tid < 18448){
        int c = tid - 18432; float s = 0.f;
        for (int i = 0; i < 128; i++) s += d_pexpsum[c*128+i];
        d_esP[c] = s;
    } else if (tid < 18464){
        int c = tid - 18448; float s = 0.f;
        for (int i = 0; i < 128; i++) s += d_ptsum[c*128+i];
        d_tsP[c] = s;
    }
}
__global__ void kB1b() {
    int tid = blockIdx.x*blockDim.x + threadIdx.x;
    if (tid < 2048){
        float S = 0.f;
        #pragma unroll
        for (int c = 0; c < 8; c++) S += d_SfP[tid*8+c];
        d_Sf[tid] = S;
        d_Df[tid] = d_SfP[tid*8] + d_SfP[tid*8+1];
    } else if (tid < 2176){
        int j = tid - 2048; float s = 0.f;
        #pragma unroll
        for (int c = 0; c < 16; c++) s += d_eorP[j*16+c];
        d_eor[j] = s;
    } else if (tid == 2176){
        float s = 0.f;
        #pragma unroll
        for (int c = 0; c < 16; c++) s += d_esP[c];
        d_es = s;
    } else if (tid == 2177){
        float s = 0.f;
        #pragma unroll
        for (int c = 0; c < 16; c++) s += d_tsP[c];
        d_ts = s;
    }
}

// ================= kB2: stats + pred + avg_tension =================
__global__ void kB2(const float* __restrict__ head_w, const float* __restrict__ head_b,
                    const int* __restrict__ stepp, float* __restrict__ out) {
    int t = threadIdx.x;
    int step = *stepp;
    if (t < 256){
        float Sfv[8];
        #pragma unroll
        for (int f = 0; f < 8; f++) Sfv[f] = d_Sf[f*256+t];
        float go = 0.f;
        #pragma unroll
        for (int f = 0; f < 8; f++) go += Sfv[f]*(1.0f/16384.0f);
        go *= 0.125f;
        d_go[t] = go;
        float gsum = 0.f;
        #pragma unroll
        for (int f = 0; f < 8; f++){
            float fm = Sfv[f]*(1.0f/16384.0f);
            d_fmean[f*256+t] = fm;
            float Tf = Sfv[f];
            if (step > 5){
                float D = d_Df[f*256+t];
                Tf += 0.15f*(4096.0f*go - 0.85f*D - 4096.0f*0.15f*fm);
            }
            gsum += Tf;
        }
        d_gmean[t] = gsum*(1.0f/131072.0f);
    }
    if (t < 128){
        float inv = 1.0f/d_es;
        float s = head_b[t];
        const float* hw = head_w + t*128;
        for (int j = 0; j < 128; j++) s = fmaf(d_eor[j]*inv, hw[j], s);
        out[t] = s;
    }
    if (t == 0) out[128] = d_ts*(1.0f/131072.0f);
}

// ================= kC2: sync/debate/pull + precomputed noise + clamp =================
__global__ void kC2(const int* __restrict__ lact, const int* __restrict__ stepp,
                    float* __restrict__ out) {
    const int cell = blockIdx.x;
    const int d = threadIdx.x;
    const int step = *stepp;
    const float gm = d_gmean[d];
    const float go = d_go[d];
    #pragma unroll
    for (int half = 0; half < 2; half++){
        int c = cell + half*65536;
        float coop = (float)lact[c];
        float v = d_hp[(size_t)c*256 + d];
        int f = c >> 14;
        v = 0.85f*v + 0.15f*d_fmean[f*256+d];
        if (step > 5 && (c & 16383) < DC) v = 0.85f*v + 0.15f*go;
        v += 0.05f*coop*(gm - v);
        v += d_noise[(size_t)c*256 + d];
        v = fminf(10.0f, fmaxf(-10.0f, v));
        out[129 + (size_t)c*256 + d] = v;
    }
}

// ================= launch (fork kNoise onto a second captured stream) =================
extern "C" void kernel_launch(void* const* d_in, const int* in_sizes, int n_in,
                              void* d_out, int out_size) {
    const float* x       = (const float*)d_in[0];
    const float* payoffs = (const float*)d_in[1];
    const int*   last    = (const int*)d_in[2];
    const int*   step    = (const int*)d_in[3];
    const float* hiddens = (const float*)d_in[4];
    const float* a_w1    = (const float*)d_in[5];
    const float* a_b1    = (const float*)d_in[6];
    const float* a_w2    = (const float*)d_in[7];
    const float* a_b2    = (const float*)d_in[8];
    const float* g_w1    = (const float*)d_in[9];
    const float* g_b1    = (const float*)d_in[10];
    const float* g_w2    = (const float*)d_in[11];
    const float* g_b2    = (const float*)d_in[12];
    const float* gru_wih = (const float*)d_in[13];
    const float* gru_whh = (const float*)d_in[14];
    const float* gru_bih = (const float*)d_in[15];
    const float* gru_bhh = (const float*)d_in[16];
    const float* head_w  = (const float*)d_in[17];
    const float* head_b  = (const float*)d_in[18];
    float* out = (float*)d_out;

    cudaFuncSetAttribute(kA, cudaFuncAttributeMaxDynamicSharedMemorySize, SMW*4);

    cudaStream_t s2;
    cudaEvent_t ev0, ev1;
    cudaStreamCreate(&s2);
    cudaEventCreateWithFlags(&ev0, cudaEventDisableTiming);
    cudaEventCreateWithFlags(&ev1, cudaEventDisableTiming);

    // fork: noise generation depends only on last_action
    cudaEventRecord(ev0, 0);
    cudaStreamWaitEvent(s2, ev0, 0);
    kNoise<<<65536, 256, 0, s2>>>(last);
    cudaEventRecord(ev1, s2);

    // main chain
    kPrep<<<512, 256>>>(x, a_w1, a_b1, g_w1, g_b1, a_w2, a_b2, g_w2, g_b2,
                        gru_wih, gru_whh, gru_bih, gru_bhh);
    kA<<<NBLK, 256, SMW*4>>>(hiddens, payoffs);
    kB1a<<<145, 128>>>();
    kB1b<<<18, 128>>>();
    kB2<<<1, 256>>>(head_w, head_b, step, out);

    // join: kC2 needs both stats and noise
    cudaStreamWaitEvent(0, ev1, 0);
    kC2<<<65536, 256>>>(last, step, out);
}

// round 11
// speedup vs baseline: 2.1443x; 1.0834x over previous
#include <cuda_runtime.h>
#include <cuda_fp16.h>
#include <cstdint>

#define NCELLS 131072
#define MC     64
#define NBLK   (NCELLS/MC)   // 2048
#define DC     4096

// ---------------- device scratch ----------------
__device__ __align__(16) uint2 d_W1h[16*32*32];        // stage1 B frags (fp16)
__device__ __align__(16) uint2 d_W2h[16*16*32];        // stage2 B frags
__device__ __align__(16) uint2 d_Wgh[4*25*4*8*32];     // GRU B frags
__device__ float d_xa[128], d_xg[128], d_b2d[128];
__device__ __align__(16) uint32_t d_hph[NCELLS*128];   // new_h as half2 pairs
__device__ __align__(16) uint32_t d_nzh[NCELLS*128];   // noise as half2 pairs
__device__ float d_pfsum[NBLK*256];
__device__ float d_pexpout[NBLK*128];
__device__ float d_pexpsum[NBLK], d_ptsum[NBLK];
__device__ float d_SfP[2048*8], d_eorP[128*16], d_esP[16], d_tsP[16];
__device__ float d_Sf[8*256], d_Df[8*256], d_eor[128], d_es, d_ts;
__device__ float d_fmean[8*256], d_go[256], d_gmean[256];

// ---------------- smem layout (u32 words) ----------------
#define HSW 132
#define OUW 76
#define S_HS 0
#define S_A2 8448
#define S_OU 16896
#define S_T  21760
#define S_E  21824
#define S_PAY 21888
#define SMW  21952        // words -> 87808 bytes

__device__ __forceinline__ uint32_t f2h2(float a, float b){
    __half2 h = __floats2half2_rn(a, b);
    return *reinterpret_cast<uint32_t*>(&h);
}
__device__ __forceinline__ float2 h2f2(uint32_t w){
    __half2 h = *reinterpret_cast<__half2*>(&w);
    return __half22float2(h);
}
__device__ __forceinline__ void mma16(float* c, const uint32_t* a, uint2 b){
    asm volatile(
        "mma.sync.aligned.m16n8k16.row.col.f32.f16.f16.f32 "
        "{%0,%1,%2,%3}, {%4,%5,%6,%7}, {%8,%9}, {%0,%1,%2,%3};"
        : "+f"(c[0]), "+f"(c[1]), "+f"(c[2]), "+f"(c[3])
        : "r"(a[0]), "r"(a[1]), "r"(a[2]), "r"(a[3]),
          "r"(b.x), "r"(b.y));
}

// GRU weight value: K-map [out 0..127 | tension 128 | ones 129 | 0 | h 144..399]
__device__ __forceinline__ float gvv(int gate, int d, int k,
        const float* wih, const float* whh, const float* bih, const float* bhh){
    if (gate <= 1){
        int r = d + (gate==1 ? 256 : 0);
        if (k < 129) return wih[r*129+k];
        if (k == 129) return bih[r]+bhh[r];
        if (k >= 144) return whh[r*256+k-144];
        return 0.f;
    } else if (gate == 2){
        int r = 512 + d;
        if (k < 129) return wih[r*129+k];
        if (k == 129) return bih[r];
        return 0.f;
    } else {
        int r = 512 + d;
        if (k == 129) return bhh[r];
        if (k >= 144) return whh[r*256+k-144];
        return 0.f;
    }
}

// ================= kPrep =================
__global__ void kPrep(const float* __restrict__ x,
                      const float* __restrict__ aw1, const float* __restrict__ ab1,
                      const float* __restrict__ gw1, const float* __restrict__ gb1,
                      const float* __restrict__ aw2, const float* __restrict__ ab2,
                      const float* __restrict__ gw2, const float* __restrict__ gb2,
                      const float* __restrict__ wih, const float* __restrict__ whh,
                      const float* __restrict__ bih, const float* __restrict__ bhh) {
    int tid = blockIdx.x*blockDim.x + threadIdx.x;
    int nth = gridDim.x*blockDim.x;
    for (int i = tid; i < 16*32*32; i += nth){
        int lane=i&31, nb=(i>>5)&31, ks=i>>10;
        int t4=lane&3, g=lane>>2;
        int n = nb*8+g;
        const float* w = (n<128)? aw1 : gw1;
        int j = n & 127;
        int k0 = ks*16 + t4*2;
        const float* r = w + j*384 + 128;
        uint2 v; v.x = f2h2(r[k0], r[k0+1]); v.y = f2h2(r[k0+8], r[k0+9]);
        d_W1h[i] = v;
    }
    for (int i = tid; i < 16*16*32; i += nth){
        int lane=i&31, nb=(i>>5)&15, ks=i>>9;
        int t4=lane&3, g=lane>>2;
        int n = nb*8+g;
        int k0 = ks*16 + t4*2;
        float vv[4];
        #pragma unroll
        for (int q = 0; q < 4; q++){
            int k = k0 + (q>>1)*8 + (q&1);
            vv[q] = (k<128)? aw2[n*128+k] : -gw2[n*128+k-128];
        }
        uint2 v; v.x = f2h2(vv[0], vv[1]); v.y = f2h2(vv[2], vv[3]);
        d_W2h[i] = v;
    }
    for (int i = tid; i < 4*25*4*8*32; i += nth){
        int lane=i&31, nb=(i>>5)&7, gate=(i>>8)&3, rest=i>>10;
        int ks = rest%25, s = rest/25;
        int t4=lane&3, g=lane>>2;
        int d = s*64 + nb*8 + g;
        int k0 = ks*16 + t4*2;
        uint2 v;
        v.x = f2h2(gvv(gate,d,k0,wih,whh,bih,bhh),   gvv(gate,d,k0+1,wih,whh,bih,bhh));
        v.y = f2h2(gvv(gate,d,k0+8,wih,whh,bih,bhh), gvv(gate,d,k0+9,wih,whh,bih,bhh));
        d_Wgh[i] = v;
    }
    if (tid < 128){
        d_b2d[tid] = ab2[tid] - gb2[tid];
        float s = ab1[tid];
        const float* w = aw1 + tid*384;
        for (int k = 0; k < 128; k++) s = fmaf(x[k], w[k], s);
        d_xa[tid] = s;
        s = gb1[tid];
        w = gw1 + tid*384;
        for (int k = 0; k < 128; k++) s = fmaf(x[k], w[k], s);
        d_xg[tid] = s;
    }
}

// ================= kA: fp16 tensor-core fused pipeline =================
__global__ __launch_bounds__(256,2)
void kA(const float* __restrict__ hiddens, const float* __restrict__ payoffs){
    extern __shared__ uint32_t smu[];
    float* smf = (float*)smu;
    const int t = threadIdx.x, b = blockIdx.x, cell0 = b*MC;
    const int warp = t>>5, lane = t&31, gid = lane>>2, tig = lane&3;

    for (int e = t; e < 64*64; e += 256){
        int row = e>>6, c4 = e&63;
        float4 v = ((const float4*)hiddens)[(size_t)(cell0+row)*64 + c4];
        smu[S_HS + row*HSW + c4*2]     = f2h2(v.x, v.y);
        smu[S_HS + row*HSW + c4*2 + 1] = f2h2(v.z, v.w);
    }
    if (t < 64) smf[S_PAY+t] = payoffs[cell0+t];
    __syncthreads();

    // ---------- stage 1 ----------
    #pragma unroll 1
    for (int pass = 0; pass < 2; pass++){
        float acc[2][4][4];
        #pragma unroll
        for (int nbI = 0; nbI < 2; nbI++){
            int nb = warp + (pass*2+nbI)*8;
            int n = nb*8 + 2*tig;
            const float* xv = (nb < 16) ? (d_xa + n) : (d_xg + n - 128);
            float i0 = xv[0], i1 = xv[1];
            #pragma unroll
            for (int mb = 0; mb < 4; mb++){
                acc[nbI][mb][0]=i0; acc[nbI][mb][1]=i1; acc[nbI][mb][2]=i0; acc[nbI][mb][3]=i1;
            }
        }
        uint2 bf[2];
        #pragma unroll
        for (int nbI = 0; nbI < 2; nbI++)
            bf[nbI] = __ldg(d_W1h + (warp + (pass*2+nbI)*8)*32 + lane);
        #pragma unroll
        for (int ks = 0; ks < 16; ks++){
            uint2 bn[2];
            if (ks < 15){
                #pragma unroll
                for (int nbI = 0; nbI < 2; nbI++)
                    bn[nbI] = __ldg(d_W1h + ((ks+1)*32 + warp + (pass*2+nbI)*8)*32 + lane);
            }
            uint32_t af[4][4];
            #pragma unroll
            for (int mb = 0; mb < 4; mb++){
                const uint32_t* ap = smu + S_HS + (mb*16+gid)*HSW + ks*8 + tig;
                af[mb][0]=ap[0]; af[mb][1]=ap[8*HSW]; af[mb][2]=ap[4]; af[mb][3]=ap[8*HSW+4];
            }
            #pragma unroll
            for (int nbI = 0; nbI < 2; nbI++)
                #pragma unroll
                for (int mb = 0; mb < 4; mb++) mma16(acc[nbI][mb], af[mb], bf[nbI]);
            bf[0]=bn[0]; bf[1]=bn[1];
        }
        #pragma unroll
        for (int nbI = 0; nbI < 2; nbI++){
            int wcol = (warp + (pass*2+nbI)*8)*4 + tig;
            #pragma unroll
            for (int mb = 0; mb < 4; mb++){
                int row = mb*16 + gid;
                smu[S_A2 + row*HSW + wcol] =
                    f2h2(fmaxf(acc[nbI][mb][0],0.f), fmaxf(acc[nbI][mb][1],0.f));
                smu[S_A2 + (row+8)*HSW + wcol] =
                    f2h2(fmaxf(acc[nbI][mb][2],0.f), fmaxf(acc[nbI][mb][3],0.f));
            }
        }
    }
    __syncthreads();

    // ---------- stage 2 ----------
    {
        float ac2[2][4][4];
        #pragma unroll
        for (int nbI = 0; nbI < 2; nbI++){
            int n = (warp + nbI*8)*8 + 2*tig;
            float i0 = d_b2d[n], i1 = d_b2d[n+1];
            #pragma unroll
            for (int mb = 0; mb < 4; mb++){
                ac2[nbI][mb][0]=i0; ac2[nbI][mb][1]=i1; ac2[nbI][mb][2]=i0; ac2[nbI][mb][3]=i1;
            }
        }
        uint2 bf[2];
        #pragma unroll
        for (int nbI = 0; nbI < 2; nbI++)
            bf[nbI] = __ldg(d_W2h + (warp + nbI*8)*32 + lane);
        #pragma unroll
        for (int ks = 0; ks < 16; ks++){
            uint2 bn[2];
            if (ks < 15){
                #pragma unroll
                for (int nbI = 0; nbI < 2; nbI++)
                    bn[nbI] = __ldg(d_W2h + ((ks+1)*16 + warp + nbI*8)*32 + lane);
            }
            uint32_t af[4][4];
            #pragma unroll
            for (int mb = 0; mb < 4; mb++){
                const uint32_t* ap = smu + S_A2 + (mb*16+gid)*HSW + ks*8 + tig;
                af[mb][0]=ap[0]; af[mb][1]=ap[8*HSW]; af[mb][2]=ap[4]; af[mb][3]=ap[8*HSW+4];
            }
            #pragma unroll
            for (int nbI = 0; nbI < 2; nbI++)
                #pragma unroll
                for (int mb = 0; mb < 4; mb++) mma16(ac2[nbI][mb], af[mb], bf[nbI]);
            bf[0]=bn[0]; bf[1]=bn[1];
        }
        #pragma unroll
        for (int nbI = 0; nbI < 2; nbI++){
            int wcol = (warp + nbI*8)*4 + tig;
            #pragma unroll
            for (int mb = 0; mb < 4; mb++){
                int row = mb*16 + gid;
                smu[S_OU + row*OUW + wcol]     = f2h2(ac2[nbI][mb][0], ac2[nbI][mb][1]);
                smu[S_OU + (row+8)*OUW + wcol] = f2h2(ac2[nbI][mb][2], ac2[nbI][mb][3]);
            }
        }
    }
    __syncthreads();

    // ---------- tension + fill K-tail cols ----------
    if (t < 64){
        float s2 = 0.f;
        const uint32_t* o = smu + S_OU + t*OUW;
        #pragma unroll 8
        for (int j = 0; j < 64; j++){
            float2 v = h2f2(o[j]);
            s2 = fmaf(v.x, v.x, s2); s2 = fmaf(v.y, v.y, s2);
        }
        s2 *= (1.0f/128.0f);
        smf[S_T+t] = s2;
        smf[S_E+t] = expf(s2);
        uint32_t* ow = smu + S_OU + t*OUW;
        ow[64] = f2h2(s2, 1.0f);
        #pragma unroll
        for (int c = 65; c < 72; c++) ow[c] = 0u;
    }
    __syncthreads();
    if (t < 128){
        float s2 = 0.f;
        int wj = t >> 1, hi = t & 1;
        for (int c = 0; c < 64; c++){
            float2 v = h2f2(smu[S_OU + c*OUW + wj]);
            s2 = fmaf(smf[S_E+c], hi ? v.y : v.x, s2);
        }
        d_pexpout[b*128+t] = s2;
    } else if (t == 128){
        float s2 = 0.f; for (int c = 0; c < 64; c++) s2 += smf[S_E+c];
        d_pexpsum[b] = s2;
    } else if (t == 129){
        float s2 = 0.f; for (int c = 0; c < 64; c++) s2 += smf[S_T+c];
        d_ptsum[b] = s2;
    }

    // ---------- GRU: 4 slices, 1 nb per warp, fused 4 gates ----------
    #pragma unroll 1
    for (int s = 0; s < 4; s++){
        float aR[4][4]={}, aZ[4][4]={}, aI[4][4]={}, aH[4][4]={};
        const uint2* wg0 = d_Wgh + ((s*25*4 + 0)*8 + warp)*32 + lane;
        uint2 bR = __ldg(wg0);
        uint2 bZ = __ldg(wg0 + 256);
        uint2 bI = __ldg(wg0 + 512);
        uint32_t af[4][4];
        #pragma unroll
        for (int mb = 0; mb < 4; mb++){
            const uint32_t* ap = smu + S_OU + (mb*16+gid)*OUW + tig;
            af[mb][0]=ap[0]; af[mb][1]=ap[8*OUW]; af[mb][2]=ap[4]; af[mb][3]=ap[8*OUW+4];
        }
        #pragma unroll
        for (int ks = 0; ks <= 8; ks++){
            uint2 bRn, bZn, bIn; uint32_t afn[4][4];
            if (ks < 8){
                const uint2* wn = wg0 + (ks+1)*1024;
                bRn = __ldg(wn); bZn = __ldg(wn + 256); bIn = __ldg(wn + 512);
                #pragma unroll
                for (int mb = 0; mb < 4; mb++){
                    const uint32_t* ap = smu + S_OU + (mb*16+gid)*OUW + (ks+1)*8 + tig;
                    afn[mb][0]=ap[0]; afn[mb][1]=ap[8*OUW]; afn[mb][2]=ap[4]; afn[mb][3]=ap[8*OUW+4];
                }
            }
            #pragma unroll
            for (int mb = 0; mb < 4; mb++){
                mma16(aR[mb], af[mb], bR);
                mma16(aZ[mb], af[mb], bZ);
                mma16(aI[mb], af[mb], bI);
            }
            if (ks == 8){
                uint2 bH8 = __ldg(wg0 + 8*1024 + 768);
                #pragma unroll
                for (int mb = 0; mb < 4; mb++) mma16(aH[mb], af[mb], bH8);
            }
            bR=bRn; bZ=bZn; bI=bIn;
            #pragma unroll
            for (int mb = 0; mb < 4; mb++)
                #pragma unroll
                for (int e2 = 0; e2 < 4; e2++) af[mb][e2] = afn[mb][e2];
        }
        {
            const uint2* w9 = wg0 + 9*1024;
            bR = __ldg(w9); bZ = __ldg(w9 + 256);
        }
        uint2 bH = __ldg(wg0 + 9*1024 + 768);
        #pragma unroll
        for (int mb = 0; mb < 4; mb++){
            const uint32_t* ap = smu + S_HS + (mb*16+gid)*HSW + tig;
            af[mb][0]=ap[0]; af[mb][1]=ap[8*HSW]; af[mb][2]=ap[4]; af[mb][3]=ap[8*HSW+4];
        }
        #pragma unroll
        for (int ks = 9; ks <= 24; ks++){
            uint2 bRn, bZn, bHn; uint32_t afn[4][4];
            if (ks < 24){
                const uint2* wn = wg0 + (ks+1)*1024;
                bRn = __ldg(wn); bZn = __ldg(wn + 256); bHn = __ldg(wn + 768);
                #pragma unroll
                for (int mb = 0; mb < 4; mb++){
                    const uint32_t* ap = smu + S_HS + (mb*16+gid)*HSW + ((ks+1)*8-72) + tig;
                    afn[mb][0]=ap[0]; afn[mb][1]=ap[8*HSW]; afn[mb][2]=ap[4]; afn[mb][3]=ap[8*HSW+4];
                }
            }
            #pragma unroll
            for (int mb = 0; mb < 4; mb++){
                mma16(aR[mb], af[mb], bR);
                mma16(aZ[mb], af[mb], bZ);
                mma16(aH[mb], af[mb], bH);
            }
            bR=bRn; bZ=bZn; bH=bHn;
            #pragma unroll
            for (int mb = 0; mb < 4; mb++)
                #pragma unroll
                for (int e2 = 0; e2 < 4; e2++) af[mb][e2] = afn[mb][e2];
        }

        int d0 = s*64 + warp*8 + 2*tig;
        float cs0 = 0.f, cs1 = 0.f;
        #pragma unroll
        for (int mb = 0; mb < 4; mb++){
            #pragma unroll
            for (int hf = 0; hf < 2; hf++){
                int row = mb*16 + gid + hf*8;
                int cell = cell0 + row;
                float2 hh = *(const float2*)(hiddens + (size_t)cell*256 + d0);
                float sc = fmaf(0.02f, smf[S_PAY+row], 0.9f);
                float v0, v1;
                {
                    int e = hf*2;
                    float r  = 1.0f/(1.0f + expf(-aR[mb][e]));
                    float z  = 1.0f/(1.0f + expf(-aZ[mb][e]));
                    float nn = tanhf(fmaf(r, aH[mb][e], aI[mb][e]));
                    v0 = ((1.0f - z)*nn + z*hh.x) * sc;
                    v0 = fminf(10.0f, fmaxf(-10.0f, v0));
                    r  = 1.0f/(1.0f + expf(-aR[mb][e+1]));
                    z  = 1.0f/(1.0f + expf(-aZ[mb][e+1]));
                    nn = tanhf(fmaf(r, aH[mb][e+1], aI[mb][e+1]));
                    v1 = ((1.0f - z)*nn + z*hh.y) * sc;
                    v1 = fminf(10.0f, fmaxf(-10.0f, v1));
                }
                d_hph[(size_t)cell*128 + (d0>>1)] = f2h2(v0, v1);
                cs0 += v0; cs1 += v1;
            }
        }
        cs0 += __shfl_xor_sync(0xffffffffu, cs0, 4);
        cs0 += __shfl_xor_sync(0xffffffffu, cs0, 8);
        cs0 += __shfl_xor_sync(0xffffffffu, cs0, 16);
        cs1 += __shfl_xor_sync(0xffffffffu, cs1, 4);
        cs1 += __shfl_xor_sync(0xffffffffu, cs1, 8);
        cs1 += __shfl_xor_sync(0xffffffffu, cs1, 16);
        if (gid == 0){
            d_pfsum[b*256 + d0]     = cs0;
            d_pfsum[b*256 + d0 + 1] = cs1;
        }
    }
}

// ================= threefry (partitionable) + XLA erf_inv =================
__device__ __forceinline__ uint32_t threefry_bits(uint32_t x0, uint32_t x1) {
    const uint32_t ks0 = 0u, ks1 = 42u, ks2 = 0x1BD11BF0u;
    x0 += ks0; x1 += ks1;
#define RND(R) { x0 += x1; x1 = (x1 << R) | (x1 >> (32 - R)); x1 ^= x0; }
    RND(13) RND(15) RND(26) RND(6)   x0 += ks1; x1 += ks2 + 1u;
    RND(17) RND(29) RND(16) RND(24)  x0 += ks2; x1 += ks0 + 2u;
    RND(13) RND(15) RND(26) RND(6)   x0 += ks0; x1 += ks1 + 3u;
    RND(17) RND(29) RND(16) RND(24)  x0 += ks1; x1 += ks2 + 4u;
    RND(13) RND(15) RND(26) RND(6)   x0 += ks2; x1 += ks0 + 5u;
#undef RND
    return x0 ^ x1;
}
__device__ __forceinline__ float erfinv_xla(float x) {
    float w = -log1pf(-x*x);
    float p;
    if (w < 5.0f){
        w -= 2.5f;
        p = 2.81022636e-08f;
        p = fmaf(p, w, 3.43273939e-07f);  p = fmaf(p, w, -3.5233877e-06f);
        p = fmaf(p, w, -4.39150654e-06f); p = fmaf(p, w, 0.00021858087f);
        p = fmaf(p, w, -0.00125372503f);  p = fmaf(p, w, -0.00417768164f);
        p = fmaf(p, w, 0.246640727f);     p = fmaf(p, w, 1.50140941f);
    } else {
        w = sqrtf(w) - 3.0f;
        p = -0.000200214257f;
        p = fmaf(p, w, 0.000100950558f);  p = fmaf(p, w, 0.00134934322f);
        p = fmaf(p, w, -0.00367342844f);  p = fmaf(p, w, 0.00573950773f);
        p = fmaf(p, w, -0.0076224613f);   p = fmaf(p, w, 0.00943887047f);
        p = fmaf(p, w, 1.00167406f);      p = fmaf(p, w, 2.83297682f);
    }
    return p*x;
}
__device__ __forceinline__ float bits_to_normal(uint32_t bits) {
    float u01 = __uint_as_float((bits >> 9) | 0x3f800000u) - 1.0f;
    float u = u01*2.0f + (-0.99999994f);
    u = fmaxf(-0.99999994f, u);
    return 1.4142135623730951f*erfinv_xla(u);
}

// ================= kNoise: depends only on last_action; fork stream =================
__global__ void kNoise(const int* __restrict__ lact){
    const int cell = blockIdx.x;      // 0..65535
    const int dp = threadIdx.x;       // 0..127 (d-pair)
    const int l0 = lact[cell];
    const int l1 = lact[cell + 65536];
    uint32_t m = (uint32_t)cell*256u + (uint32_t)(dp*2);
    uint32_t w0 = 0u, w1 = 0u;
    if (!l0){
        float a = 0.02f*bits_to_normal(threefry_bits(0u, m));
        float bq = 0.02f*bits_to_normal(threefry_bits(0u, m + 1u));
        w0 = f2h2(a, bq);
    }
    if (!l1){
        float a = 0.02f*bits_to_normal(threefry_bits(0u, m + 16777216u));
        float bq = 0.02f*bits_to_normal(threefry_bits(0u, m + 16777217u));
        w1 = f2h2(a, bq);
    }
    d_nzh[(size_t)cell*128 + dp] = w0;
    d_nzh[(size_t)(cell+65536)*128 + dp] = w1;
}

// ================= kB1a: coalesced partial reductions =================
__global__ void kB1a() {
    const int b = blockIdx.x, t = threadIdx.x;
    if (b < 64){
        // faction partials: f = b>>3, chunk c = b&7, rows c*32..c*32+31
        int f = b >> 3, c = b & 7;
        const float* p = d_pfsum + (size_t)(f*256 + c*32)*256 + t;
        float S = 0.f;
        #pragma unroll 8
        for (int i = 0; i < 32; i++) S += p[(size_t)i*256];
        d_SfP[(f*256 + t)*8 + c] = S;
    } else if (b < 80){
        // expout partials: chunk c = b-64, rows c*128..c*128+127; t<128 = j
        if (t < 128){
            int c = b - 64;
            const float* p = d_pexpout + (size_t)(c*128)*128 + t;
            float s = 0.f;
            #pragma unroll 8
            for (int i = 0; i < 128; i++) s += p[(size_t)i*128];
            d_eorP[t*16 + c] = s;
        }
    } else {
        if (t < 16){
            float s = 0.f;
            for (int i = 0; i < 128; i++) s += d_pexpsum[t*128+i];
            d_esP[t] = s;
        } else if (t < 32){
            int c = t - 16; float s = 0.f;
            for (int i = 0; i < 128; i++) s += d_ptsum[c*128+i];
            d_tsP[c] = s;
        }
    }
}
__global__ void kB1b() {
    int tid = blockIdx.x*blockDim.x + threadIdx.x;
    if (tid < 2048){
        float S = 0.f;
        #pragma unroll
        for (int c = 0; c < 8; c++) S += d_SfP[tid*8+c];
        d_Sf[tid] = S;
        d_Df[tid] = d_SfP[tid*8] + d_SfP[tid*8+1];
    } else if (tid < 2176){
        int j = tid - 2048; float s = 0.f;
        #pragma unroll
        for (int c = 0; c < 16; c++) s += d_eorP[j*16+c];
        d_eor[j] = s;
    } else if (tid == 2176){
        float s = 0.f;
        #pragma unroll
        for (int c = 0; c < 16; c++) s += d_esP[c];
        d_es = s;
    } else if (tid == 2177){
        float s = 0.f;
        #pragma unroll
        for (int c = 0; c < 16; c++) s += d_tsP[c];
        d_ts = s;
    }
}

// ================= kB2: stats + pred + avg_tension =================
__global__ void kB2(const float* __restrict__ head_w, const float* __restrict__ head_b,
                    const int* __restrict__ stepp, float* __restrict__ out) {
    int t = threadIdx.x;
    int step = *stepp;
    if (t < 256){
        float Sfv[8];
        #pragma unroll
        for (int f = 0; f < 8; f++) Sfv[f] = d_Sf[f*256+t];
        float go = 0.f;
        #pragma unroll
        for (int f = 0; f < 8; f++) go += Sfv[f]*(1.0f/16384.0f);
        go *= 0.125f;
        d_go[t] = go;
        float gsum = 0.f;
        #pragma unroll
        for (int f = 0; f < 8; f++){
            float fm = Sfv[f]*(1.0f/16384.0f);
            d_fmean[f*256+t] = fm;
            float Tf = Sfv[f];
            if (step > 5){
                float D = d_Df[f*256+t];
                Tf += 0.15f*(4096.0f*go - 0.85f*D - 4096.0f*0.15f*fm);
            }
            gsum += Tf;
        }
        d_gmean[t] = gsum*(1.0f/131072.0f);
    }
    if (t < 128){
        float inv = 1.0f/d_es;
        float s = head_b[t];
        const float* hw = head_w + t*128;
        for (int j = 0; j < 128; j++) s = fmaf(d_eor[j]*inv, hw[j], s);
        out[t] = s;
    }
    if (t == 0) out[128] = d_ts*(1.0f/131072.0f);
}

// ================= kC2: sync/debate/pull + noise + clamp (half2 streams) =================
__global__ void kC2(const int* __restrict__ lact, const int* __restrict__ stepp,
                    float* __restrict__ out) {
    const int cell = blockIdx.x;      // 0..65535
    const int dp = threadIdx.x;       // 0..127
    const int step = *stepp;
    const float gm0 = d_gmean[dp*2],  gm1 = d_gmean[dp*2+1];
    const float go0 = d_go[dp*2],     go1 = d_go[dp*2+1];
    #pragma unroll
    for (int half = 0; half < 2; half++){
        int c = cell + half*65536;
        float coop = (float)lact[c];
        int f = c >> 14;
        float2 hp = h2f2(d_hph[(size_t)c*128 + dp]);
        float2 nz = h2f2(d_nzh[(size_t)c*128 + dp]);
        float fm0 = d_fmean[f*256 + dp*2], fm1 = d_fmean[f*256 + dp*2 + 1];
        float v0 = 0.85f*hp.x + 0.15f*fm0;
        float v1 = 0.85f*hp.y + 0.15f*fm1;
        if (step > 5 && (c & 16383) < DC){
            v0 = 0.85f*v0 + 0.15f*go0;
            v1 = 0.85f*v1 + 0.15f*go1;
        }
        v0 += 0.05f*coop*(gm0 - v0);
        v1 += 0.05f*coop*(gm1 - v1);
        v0 += nz.x; v1 += nz.y;
        v0 = fminf(10.0f, fmaxf(-10.0f, v0));
        v1 = fminf(10.0f, fmaxf(-10.0f, v1));
        out[129 + (size_t)c*256 + dp*2]     = v0;
        out[129 + (size_t)c*256 + dp*2 + 1] = v1;
    }
}

// ================= launch (fork kNoise onto a second captured stream) =================
extern "C" void kernel_launch(void* const* d_in, const int* in_sizes, int n_in,
                              void* d_out, int out_size) {
    const float* x       = (const float*)d_in[0];
    const float* payoffs = (const float*)d_in[1];
    const int*   last    = (const int*)d_in[2];
    const int*   step    = (const int*)d_in[3];
    const float* hiddens = (const float*)d_in[4];
    const float* a_w1    = (const float*)d_in[5];
    const float* a_b1    = (const float*)d_in[6];
    const float* a_w2    = (const float*)d_in[7];
    const float* a_b2    = (const float*)d_in[8];
    const float* g_w1    = (const float*)d_in[9];
    const float* g_b1    = (const float*)d_in[10];
    const float* g_w2    = (const float*)d_in[11];
    const float* g_b2    = (const float*)d_in[12];
    const float* gru_wih = (const float*)d_in[13];
    const float* gru_whh = (const float*)d_in[14];
    const float* gru_bih = (const float*)d_in[15];
    const float* gru_bhh = (const float*)d_in[16];
    const float* head_w  = (const float*)d_in[17];
    const float* head_b  = (const float*)d_in[18];
    float* out = (float*)d_out;

    cudaFuncSetAttribute(kA, cudaFuncAttributeMaxDynamicSharedMemorySize, SMW*4);

    cudaStream_t s2;
    cudaEvent_t ev0, ev1;
    cudaStreamCreate(&s2);
    cudaEventCreateWithFlags(&ev0, cudaEventDisableTiming);
    cudaEventCreateWithFlags(&ev1, cudaEventDisableTiming);

    // fork: noise generation depends only on last_action
    cudaEventRecord(ev0, 0);
    cudaStreamWaitEvent(s2, ev0, 0);
    kNoise<<<65536, 128, 0, s2>>>(last);
    cudaEventRecord(ev1, s2);

    // main chain
    kPrep<<<512, 256>>>(x, a_w1, a_b1, g_w1, g_b1, a_w2, a_b2, g_w2, g_b2,
                        gru_wih, gru_whh, gru_bih, gru_bhh);
    kA<<<NBLK, 256, SMW*4>>>(hiddens, payoffs);
    kB1a<<<81, 256>>>();
    kB1b<<<18, 128>>>();
    kB2<<<1, 256>>>(head_w, head_b, step, out);

    // join: kC2 needs both stats and noise
    cudaStreamWaitEvent(0, ev1, 0);
    kC2<<<65536, 128>>>(last, step, out);
}